// round 1
// baseline (speedup 1.0000x reference)
#include <cuda_runtime.h>
#include <math.h>

// ---------------- problem constants ----------------
#define T_TOK 4096
#define B_SZ  16
#define CIN   256
#define HEADS 8
#define HDIM  32
#define HD    256          // HEADS*HDIM
#define SIDE  64
#define M_CT  16           // PW*PH
#define BH    128          // B*HEADS
#define NROWS (T_TOK * B_SZ)   // 65536

// ---------------- scratch (static device globals; no allocs allowed) ----------------
__device__ float g_q[(size_t)BH * T_TOK * HDIM];    // q_tok [BH][T][D]   64 MB
__device__ float g_v[(size_t)BH * T_TOK * HDIM];    // v_tok [BH][T][D]   64 MB
__device__ float g_chat[BH * M_CT * HDIM];          // normalized centers
__device__ float g_vc[BH * M_CT * HDIM];            // value centers (raw)
__device__ float g_co[BH * M_CT * HDIM];            // centers_out
__device__ float g_w[(size_t)BH * T_TOK * 2];       // per-token top2 weights (normalized)
__device__ int   g_sel[(size_t)BH * T_TOK];         // packed i0 | i1<<8
__device__ float g_ot[(size_t)NROWS * HD];          // out_tok in [T,B,HD] row layout  64 MB

// ---------------- GEMM: C[n,j] = sum_c A[n,c]*W[j,c] + bias[j] ----------------
// A: [NROWS, 256] row-major.  W row-major [cols, 256].
// mode 0: cols = 512 (q weights then v weights); epilogue scatters into g_q/g_v [BH][T][D].
// mode 1: cols = 256 (proj);     A = g_ot; epilogue writes outPlain[n*256 + j]  (== [T,B,C]).
__global__ __launch_bounds__(256, 2)
void k_gemm(const float* __restrict__ A,
            const float* __restrict__ Wq, const float* __restrict__ bq,
            const float* __restrict__ Wv, const float* __restrict__ bv,
            float* __restrict__ outPlain, int mode)
{
    __shared__ float As[8][128];
    __shared__ float Ws[8][128];

    if (mode == 1) A = g_ot;

    const int tid = threadIdx.x;
    const int rowBase = blockIdx.x * 128;
    const int colBase0 = blockIdx.y * 128;

    const float* W;
    const float* bias;
    int colBase;
    if (colBase0 < 256) { W = Wq; bias = bq; colBase = colBase0; }
    else                { W = Wv; bias = bv; colBase = colBase0 - 256; }

    const int ldr = tid >> 1;          // 0..127 (row within tile)
    const int ldp = (tid & 1) * 4;     // 0 or 4  (k-offset of float4)
    const int tx  = tid & 15;
    const int ty  = tid >> 4;

    float acc[8][8];
#pragma unroll
    for (int i = 0; i < 8; i++)
#pragma unroll
        for (int j = 0; j < 8; j++) acc[i][j] = 0.f;

    for (int kt = 0; kt < CIN; kt += 8) {
        float4 av = *(const float4*)(A + (size_t)(rowBase + ldr) * CIN + kt + ldp);
        float4 wv = *(const float4*)(W + (size_t)(colBase + ldr) * CIN + kt + ldp);
        __syncthreads();
        As[ldp + 0][ldr] = av.x; As[ldp + 1][ldr] = av.y;
        As[ldp + 2][ldr] = av.z; As[ldp + 3][ldr] = av.w;
        Ws[ldp + 0][ldr] = wv.x; Ws[ldp + 1][ldr] = wv.y;
        Ws[ldp + 2][ldr] = wv.z; Ws[ldp + 3][ldr] = wv.w;
        __syncthreads();
#pragma unroll
        for (int k = 0; k < 8; k++) {
            float4 a0 = *(const float4*)&As[k][ty * 4];
            float4 a1 = *(const float4*)&As[k][ty * 4 + 64];
            float4 b0 = *(const float4*)&Ws[k][tx * 4];
            float4 b1 = *(const float4*)&Ws[k][tx * 4 + 64];
            float ar[8] = {a0.x, a0.y, a0.z, a0.w, a1.x, a1.y, a1.z, a1.w};
            float br[8] = {b0.x, b0.y, b0.z, b0.w, b1.x, b1.y, b1.z, b1.w};
#pragma unroll
            for (int i = 0; i < 8; i++)
#pragma unroll
                for (int j = 0; j < 8; j++)
                    acc[i][j] = fmaf(ar[i], br[j], acc[i][j]);
        }
    }

    // epilogue
#pragma unroll
    for (int i = 0; i < 8; i++) {
        const int n = rowBase + ((i < 4) ? (ty * 4 + i) : (64 + ty * 4 + (i - 4)));
#pragma unroll
        for (int g = 0; g < 2; g++) {
            const int cLoc = colBase + g * 64 + tx * 4;   // col within chosen W (0..255)
            float4 r;
            r.x = acc[i][g * 4 + 0] + bias[cLoc + 0];
            r.y = acc[i][g * 4 + 1] + bias[cLoc + 1];
            r.z = acc[i][g * 4 + 2] + bias[cLoc + 2];
            r.w = acc[i][g * 4 + 3] + bias[cLoc + 3];
            if (mode == 1) {
                *(float4*)(outPlain + (size_t)n * HD + cLoc) = r;
            } else {
                const int t = n >> 4, b = n & 15;
                const int h = cLoc >> 5, d = cLoc & 31;
                float* dst = (colBase0 < 256) ? g_q : g_v;
                *(float4*)(dst + ((((size_t)b * HEADS + h) * T_TOK + t) * HDIM + d)) = r;
            }
        }
    }
}

// ---------------- pooling: centers (normalized) + value centers ----------------
// grid = BH*M_CT blocks, 256 threads
__global__ void k_pool()
{
    const int bh = blockIdx.x >> 4;
    const int m  = blockIdx.x & 15;
    const int py = m >> 2, px = m & 3;
    const int ti = threadIdx.x >> 5;   // 0..7
    const int d  = threadIdx.x & 31;

    float sq = 0.f, sv = 0.f;
    for (int j = ti; j < 256; j += 8) {
        const int yi = j >> 4, xi = j & 15;
        const int t = (py * 16 + yi) * SIDE + px * 16 + xi;
        const size_t off = ((size_t)bh * T_TOK + t) * HDIM + d;
        sq += g_q[off];
        sv += g_v[off];
    }
    __shared__ float shq[8][32], shv[8][32];
    shq[ti][d] = sq; shv[ti][d] = sv;
    __syncthreads();
    if (threadIdx.x < 32) {
        const int dd = threadIdx.x;
        float aq = 0.f, av = 0.f;
#pragma unroll
        for (int i = 0; i < 8; i++) { aq += shq[i][dd]; av += shv[i][dd]; }
        aq *= (1.f / 256.f); av *= (1.f / 256.f);
        float nn = aq * aq;
#pragma unroll
        for (int o = 16; o; o >>= 1) nn += __shfl_xor_sync(0xffffffffu, nn, o);
        const float denom = fmaxf(sqrtf(nn), 1e-12f);
        g_chat[bh * (M_CT * HDIM) + m * HDIM + dd] = aq / denom;
        g_vc[bh * (M_CT * HDIM) + m * HDIM + dd] = av;
    }
}

// ---------------- similarity + top-2 + normalized weights ----------------
// grid (BH, T/256), 256 threads
__global__ void k_sim(const float* __restrict__ alpha, const float* __restrict__ beta)
{
    const int bh = blockIdx.x;
    const int t = blockIdx.y * 256 + threadIdx.x;
    __shared__ float ch[M_CT * HDIM];
    ch[threadIdx.x] = g_chat[bh * 512 + threadIdx.x];
    ch[256 + threadIdx.x] = g_chat[bh * 512 + 256 + threadIdx.x];
    __syncthreads();

    float q[32];
    const float* qp = g_q + ((size_t)bh * T_TOK + t) * HDIM;
#pragma unroll
    for (int i = 0; i < 8; i++) {
        float4 v4 = *(const float4*)(qp + i * 4);
        q[i * 4 + 0] = v4.x; q[i * 4 + 1] = v4.y; q[i * 4 + 2] = v4.z; q[i * 4 + 3] = v4.w;
    }
    float qn = 0.f;
#pragma unroll
    for (int d = 0; d < 32; d++) qn += q[d] * q[d];
    const float rq = 1.f / fmaxf(sqrtf(qn), 1e-12f);
    const float a = alpha[0], b = beta[0];

    float s[16];
#pragma unroll
    for (int m = 0; m < 16; m++) {
        float dot = 0.f;
#pragma unroll
        for (int d = 0; d < 32; d++) dot = fmaf(ch[m * 32 + d], q[d], dot);
        const float z = b + a * (dot * rq);
        s[m] = 1.f / (1.f + expf(-z));
    }
    // top-2 (first-occurrence ties, matching lax.top_k)
    int i0 = 0; float v0 = s[0];
#pragma unroll
    for (int m = 1; m < 16; m++) if (s[m] > v0) { v0 = s[m]; i0 = m; }
    int i1 = -1; float v1 = -1.f;
#pragma unroll
    for (int m = 0; m < 16; m++) if (m != i0 && s[m] > v1) { v1 = s[m]; i1 = m; }

    const float p0 = v0 * v0, p1 = v1 * v1;
    const float inv = 1.f / (p0 + p1 + 1e-6f);
    const size_t o = (size_t)bh * T_TOK + t;
    g_w[o * 2 + 0] = p0 * inv;
    g_w[o * 2 + 1] = p1 * inv;
    g_sel[o] = i0 | (i1 << 8);
}

// ---------------- centers_out: sparse scatter-reduce over tokens ----------------
// grid = BH blocks, 256 threads (8 warps, warp-private smem accumulators)
__global__ __launch_bounds__(256)
void k_centers()
{
    const int bh = blockIdx.x;
    __shared__ float acc[8][16][32];
    __shared__ float cnt[8][16];
    __shared__ float ctot[16];
    const int tid = threadIdx.x;
    for (int i = tid; i < 8 * 16 * 32; i += 256) ((float*)acc)[i] = 0.f;
    if (tid < 128) ((float*)cnt)[tid] = 0.f;
    __syncthreads();

    const int wi = tid >> 5, lane = tid & 31;
    for (int t = wi; t < T_TOK; t += 8) {
        const size_t o = (size_t)bh * T_TOK + t;
        const float vv = g_v[o * HDIM + lane];
        const float w0 = g_w[o * 2 + 0];
        const float w1 = g_w[o * 2 + 1];
        const int sel = g_sel[o];
        const int i0 = sel & 255, i1 = sel >> 8;
        acc[wi][i0][lane] += w0 * vv;
        acc[wi][i1][lane] += w1 * vv;
        if (lane == 0) { cnt[wi][i0] += w0; cnt[wi][i1] += w1; }
    }
    __syncthreads();
    if (tid < 16) {
        float c = 0.f;
#pragma unroll
        for (int i = 0; i < 8; i++) c += cnt[i][tid];
        ctot[tid] = c;
    }
    __syncthreads();
    for (int i = tid; i < 512; i += 256) {
        const int m = i >> 5;
        float ssum = 0.f;
#pragma unroll
        for (int wj = 0; wj < 8; wj++) ssum += acc[wj][m][i & 31];
        g_co[bh * 512 + i] = (ssum + g_vc[bh * 512 + i]) / (ctot[m] + 1.f);
    }
}

// ---------------- out_tok = w0*co[i0] + w1*co[i1], written in GEMM-ready layout ----------------
// grid (BH, T/256), 256 threads
__global__ void k_ot()
{
    const int bh = blockIdx.x;
    const int t = blockIdx.y * 256 + threadIdx.x;
    __shared__ float co[16][33];   // padded: banks (m+d)%32 -> conflict-free gather
    {
        const int m = threadIdx.x >> 5, d = threadIdx.x & 31;
        co[m][d]     = g_co[bh * 512 + threadIdx.x];
        co[m + 8][d] = g_co[bh * 512 + 256 + threadIdx.x];
    }
    __syncthreads();
    const size_t o = (size_t)bh * T_TOK + t;
    const float w0 = g_w[o * 2 + 0];
    const float w1 = g_w[o * 2 + 1];
    const int sel = g_sel[o];
    const int i0 = sel & 255, i1 = sel >> 8;
    const int b = bh >> 3, h = bh & 7;
    float* dst = g_ot + ((size_t)t * B_SZ + b) * HD + h * HDIM;
#pragma unroll
    for (int d4 = 0; d4 < 8; d4++) {
        float4 r;
        r.x = w0 * co[i0][d4 * 4 + 0] + w1 * co[i1][d4 * 4 + 0];
        r.y = w0 * co[i0][d4 * 4 + 1] + w1 * co[i1][d4 * 4 + 1];
        r.z = w0 * co[i0][d4 * 4 + 2] + w1 * co[i1][d4 * 4 + 2];
        r.w = w0 * co[i0][d4 * 4 + 3] + w1 * co[i1][d4 * 4 + 3];
        *(float4*)(dst + d4 * 4) = r;
    }
}

// ---------------- launch ----------------
extern "C" void kernel_launch(void* const* d_in, const int* in_sizes, int n_in,
                              void* d_out, int out_size)
{
    const float* x      = (const float*)d_in[0];   // [T,B,C]
    const float* f_w    = (const float*)d_in[1];   // [256,256]
    const float* f_b    = (const float*)d_in[2];
    const float* v_w    = (const float*)d_in[3];
    const float* v_b    = (const float*)d_in[4];
    const float* proj_w = (const float*)d_in[5];
    const float* proj_b = (const float*)d_in[6];
    const float* alpha  = (const float*)d_in[7];
    const float* beta   = (const float*)d_in[8];
    float* out = (float*)d_out;

    // 1) q/v GEMM: [65536,256] x [256,512]^T -> g_q, g_v in [BH][T][D]
    k_gemm<<<dim3(NROWS / 128, 4), 256>>>(x, f_w, f_b, v_w, v_b, nullptr, 0);
    // 2) pooling -> normalized centers + value centers
    k_pool<<<BH * M_CT, 256>>>();
    // 3) similarity + top2 + weights
    k_sim<<<dim3(BH, T_TOK / 256), 256>>>(alpha, beta);
    // 4) centers_out
    k_centers<<<BH, 256>>>();
    // 5) out_tok in [T,B,HD] layout
    k_ot<<<dim3(BH, T_TOK / 256), 256>>>();
    // 6) projection GEMM -> output [T,B,C]
    k_gemm<<<dim3(NROWS / 128, 2), 256>>>(nullptr, proj_w, proj_b, nullptr, nullptr, out, 1);
}

// round 2
// speedup vs baseline: 1.0724x; 1.0724x over previous
#include <cuda_runtime.h>
#include <math.h>

// ---------------- problem constants ----------------
#define T_TOK 4096
#define B_SZ  16
#define CIN   256
#define HEADS 8
#define HDIM  32
#define HD    256          // HEADS*HDIM
#define SIDE  64
#define M_CT  16           // PW*PH
#define BH    128          // B*HEADS
#define NROWS (T_TOK * B_SZ)   // 65536
#define CSPLIT 4           // token splits for k_centers

// ---------------- scratch ----------------
__device__ float g_q[(size_t)BH * T_TOK * HDIM];
__device__ float g_v[(size_t)BH * T_TOK * HDIM];
__device__ float g_chat[BH * M_CT * HDIM];
__device__ float g_vc[BH * M_CT * HDIM];
__device__ float g_co[BH * M_CT * HDIM];
__device__ float g_coacc[BH * M_CT * HDIM];
__device__ float g_cnt[BH * M_CT];
__device__ float g_w[(size_t)BH * T_TOK * 2];
__device__ int   g_sel[(size_t)BH * T_TOK];
__device__ float g_ot[(size_t)NROWS * HD];

// ---------------- f32x2 helpers (Blackwell packed fp32) ----------------
__device__ __forceinline__ unsigned long long pk2(float lo, float hi) {
    unsigned long long r;
    asm("mov.b64 %0,{%1,%2};" : "=l"(r) : "f"(lo), "f"(hi));
    return r;
}
__device__ __forceinline__ unsigned long long dup2(float v) {
    unsigned long long r;
    asm("mov.b64 %0,{%1,%1};" : "=l"(r) : "f"(v));
    return r;
}
__device__ __forceinline__ unsigned long long fma2(unsigned long long a,
                                                   unsigned long long b,
                                                   unsigned long long c) {
    unsigned long long d;
    asm("fma.rn.f32x2 %0,%1,%2,%3;" : "=l"(d) : "l"(a), "l"(b), "l"(c));
    return d;
}
__device__ __forceinline__ float2 upk2(unsigned long long v) {
    float2 f;
    asm("mov.b64 {%0,%1},%2;" : "=f"(f.x), "=f"(f.y) : "l"(v));
    return f;
}

// ---------------- GEMM with FMA2 inner loop ----------------
// C[n,j] = sum_c A[n,c]*W[j,c] + bias[j]
// mode 0: two 256-wide weight sets (q then v), scatter epilogue into g_q/g_v
// mode 1: 256-wide proj, A = g_ot, plain row-major output
__global__ __launch_bounds__(256, 2)
void k_gemm(const float* __restrict__ A,
            const float* __restrict__ Wq, const float* __restrict__ bq,
            const float* __restrict__ Wv, const float* __restrict__ bv,
            float* __restrict__ outPlain, int mode)
{
    __shared__ float As[8][128];
    __shared__ float Ws[8][128];

    if (mode == 1) A = g_ot;

    const int tid = threadIdx.x;
    const int rowBase = blockIdx.x * 128;
    const int colBase0 = blockIdx.y * 128;

    const float* W;
    const float* bias;
    int colBase;
    if (colBase0 < 256) { W = Wq; bias = bq; colBase = colBase0; }
    else                { W = Wv; bias = bv; colBase = colBase0 - 256; }

    const int ldr = tid >> 1;
    const int ldp = (tid & 1) * 4;
    const int tx  = tid & 15;
    const int ty  = tid >> 4;

    // acc2[p][j]: row-pair p (2 rows packed in f32x2), col j
    unsigned long long acc2[4][8];
#pragma unroll
    for (int p = 0; p < 4; p++)
#pragma unroll
        for (int j = 0; j < 8; j++) acc2[p][j] = 0ull;

    for (int kt = 0; kt < CIN; kt += 8) {
        float4 av = *(const float4*)(A + (size_t)(rowBase + ldr) * CIN + kt + ldp);
        float4 wv = *(const float4*)(W + (size_t)(colBase + ldr) * CIN + kt + ldp);
        __syncthreads();
        As[ldp + 0][ldr] = av.x; As[ldp + 1][ldr] = av.y;
        As[ldp + 2][ldr] = av.z; As[ldp + 3][ldr] = av.w;
        Ws[ldp + 0][ldr] = wv.x; Ws[ldp + 1][ldr] = wv.y;
        Ws[ldp + 2][ldr] = wv.z; Ws[ldp + 3][ldr] = wv.w;
        __syncthreads();
#pragma unroll
        for (int k = 0; k < 8; k++) {
            float4 a0 = *(const float4*)&As[k][ty * 4];
            float4 a1 = *(const float4*)&As[k][ty * 4 + 64];
            float4 b0 = *(const float4*)&Ws[k][tx * 4];
            float4 b1 = *(const float4*)&Ws[k][tx * 4 + 64];
            unsigned long long a2[4];
            a2[0] = pk2(a0.x, a0.y); a2[1] = pk2(a0.z, a0.w);
            a2[2] = pk2(a1.x, a1.y); a2[3] = pk2(a1.z, a1.w);
            float br[8] = {b0.x, b0.y, b0.z, b0.w, b1.x, b1.y, b1.z, b1.w};
#pragma unroll
            for (int j = 0; j < 8; j++) {
                unsigned long long bd = dup2(br[j]);
#pragma unroll
                for (int p = 0; p < 4; p++)
                    acc2[p][j] = fma2(a2[p], bd, acc2[p][j]);
            }
        }
    }

    // unpack to acc[8][8] (same layout as the scalar version)
    float acc[8][8];
#pragma unroll
    for (int p = 0; p < 4; p++)
#pragma unroll
        for (int j = 0; j < 8; j++) {
            float2 f = upk2(acc2[p][j]);
            acc[2 * p + 0][j] = f.x;
            acc[2 * p + 1][j] = f.y;
        }

#pragma unroll
    for (int i = 0; i < 8; i++) {
        const int n = rowBase + ((i < 4) ? (ty * 4 + i) : (64 + ty * 4 + (i - 4)));
#pragma unroll
        for (int g = 0; g < 2; g++) {
            const int cLoc = colBase + g * 64 + tx * 4;
            float4 r;
            r.x = acc[i][g * 4 + 0] + bias[cLoc + 0];
            r.y = acc[i][g * 4 + 1] + bias[cLoc + 1];
            r.z = acc[i][g * 4 + 2] + bias[cLoc + 2];
            r.w = acc[i][g * 4 + 3] + bias[cLoc + 3];
            if (mode == 1) {
                *(float4*)(outPlain + (size_t)n * HD + cLoc) = r;
            } else {
                const int t = n >> 4, b = n & 15;
                const int h = cLoc >> 5, d = cLoc & 31;
                float* dst = (colBase0 < 256) ? g_q : g_v;
                *(float4*)(dst + ((((size_t)b * HEADS + h) * T_TOK + t) * HDIM + d)) = r;
            }
        }
    }
}

// ---------------- zero the center accumulators ----------------
__global__ void k_zero()
{
    const int i = blockIdx.x * 256 + threadIdx.x;
    g_coacc[i] = 0.f;
    if (i < BH * M_CT) g_cnt[i] = 0.f;
}

// ---------------- pooling ----------------
__global__ void k_pool()
{
    const int bh = blockIdx.x >> 4;
    const int m  = blockIdx.x & 15;
    const int py = m >> 2, px = m & 3;
    const int ti = threadIdx.x >> 5;
    const int d  = threadIdx.x & 31;

    float sq = 0.f, sv = 0.f;
    for (int j = ti; j < 256; j += 8) {
        const int yi = j >> 4, xi = j & 15;
        const int t = (py * 16 + yi) * SIDE + px * 16 + xi;
        const size_t off = ((size_t)bh * T_TOK + t) * HDIM + d;
        sq += g_q[off];
        sv += g_v[off];
    }
    __shared__ float shq[8][32], shv[8][32];
    shq[ti][d] = sq; shv[ti][d] = sv;
    __syncthreads();
    if (threadIdx.x < 32) {
        const int dd = threadIdx.x;
        float aq = 0.f, av = 0.f;
#pragma unroll
        for (int i = 0; i < 8; i++) { aq += shq[i][dd]; av += shv[i][dd]; }
        aq *= (1.f / 256.f); av *= (1.f / 256.f);
        float nn = aq * aq;
#pragma unroll
        for (int o = 16; o; o >>= 1) nn += __shfl_xor_sync(0xffffffffu, nn, o);
        const float denom = fmaxf(sqrtf(nn), 1e-12f);
        g_chat[bh * (M_CT * HDIM) + m * HDIM + dd] = aq / denom;
        g_vc[bh * (M_CT * HDIM) + m * HDIM + dd] = av;
    }
}

// ---------------- similarity + top-2 ----------------
__global__ void k_sim(const float* __restrict__ alpha, const float* __restrict__ beta)
{
    const int bh = blockIdx.x;
    const int t = blockIdx.y * 256 + threadIdx.x;
    __shared__ float ch[M_CT * HDIM];
    ch[threadIdx.x] = g_chat[bh * 512 + threadIdx.x];
    ch[256 + threadIdx.x] = g_chat[bh * 512 + 256 + threadIdx.x];
    __syncthreads();

    float q[32];
    const float* qp = g_q + ((size_t)bh * T_TOK + t) * HDIM;
#pragma unroll
    for (int i = 0; i < 8; i++) {
        float4 v4 = *(const float4*)(qp + i * 4);
        q[i * 4 + 0] = v4.x; q[i * 4 + 1] = v4.y; q[i * 4 + 2] = v4.z; q[i * 4 + 3] = v4.w;
    }
    float qn = 0.f;
#pragma unroll
    for (int d = 0; d < 32; d++) qn += q[d] * q[d];
    const float rq = 1.f / fmaxf(sqrtf(qn), 1e-12f);
    const float a = alpha[0], b = beta[0];

    float s[16];
#pragma unroll
    for (int m = 0; m < 16; m++) {
        float dot = 0.f;
#pragma unroll
        for (int d = 0; d < 32; d++) dot = fmaf(ch[m * 32 + d], q[d], dot);
        const float z = b + a * (dot * rq);
        s[m] = 1.f / (1.f + expf(-z));
    }
    int i0 = 0; float v0 = s[0];
#pragma unroll
    for (int m = 1; m < 16; m++) if (s[m] > v0) { v0 = s[m]; i0 = m; }
    int i1 = -1; float v1 = -1.f;
#pragma unroll
    for (int m = 0; m < 16; m++) if (m != i0 && s[m] > v1) { v1 = s[m]; i1 = m; }

    const float p0 = v0 * v0, p1 = v1 * v1;
    const float inv = 1.f / (p0 + p1 + 1e-6f);
    const size_t o = (size_t)bh * T_TOK + t;
    g_w[o * 2 + 0] = p0 * inv;
    g_w[o * 2 + 1] = p1 * inv;
    g_sel[o] = i0 | (i1 << 8);
}

// ---------------- centers_out partial sums: register accumulators ----------------
// grid (BH, CSPLIT), 256 threads (8 warps). Warp processes tokens, lane = d.
__global__ __launch_bounds__(256)
void k_centers()
{
    const int bh = blockIdx.x;
    const int tBase = blockIdx.y * (T_TOK / CSPLIT);
    const int wi = threadIdx.x >> 5, lane = threadIdx.x & 31;

    float acc[16], wacc[16];
#pragma unroll
    for (int m = 0; m < 16; m++) { acc[m] = 0.f; wacc[m] = 0.f; }

#pragma unroll 2
    for (int t = tBase + wi; t < tBase + T_TOK / CSPLIT; t += 8) {
        const size_t o = (size_t)bh * T_TOK + t;
        const float vv = g_v[o * HDIM + lane];
        const float2 w01 = *(const float2*)(g_w + o * 2);
        const int sel = g_sel[o];
        const int i0 = sel & 255, i1 = sel >> 8;
#pragma unroll
        for (int m = 0; m < 16; m++) {
            const float w = (m == i0) ? w01.x : ((m == i1) ? w01.y : 0.f);
            acc[m] = fmaf(w, vv, acc[m]);
            wacc[m] += w;
        }
    }

    __shared__ float sacc[8][16][32];
    __shared__ float swacc[8][16];
#pragma unroll
    for (int m = 0; m < 16; m++) sacc[wi][m][lane] = acc[m];
    if (lane == 0) {
#pragma unroll
        for (int m = 0; m < 16; m++) swacc[wi][m] = wacc[m];
    }
    __syncthreads();

    for (int i = threadIdx.x; i < 512; i += 256) {
        const int m = i >> 5, d = i & 31;
        float s = 0.f;
#pragma unroll
        for (int w = 0; w < 8; w++) s += sacc[w][m][d];
        atomicAdd(&g_coacc[bh * 512 + i], s);
    }
    if (threadIdx.x < 16) {
        float s = 0.f;
#pragma unroll
        for (int w = 0; w < 8; w++) s += swacc[w][threadIdx.x];
        atomicAdd(&g_cnt[bh * 16 + threadIdx.x], s);
    }
}

// ---------------- finalize centers_out ----------------
__global__ void k_cofin()
{
    const int i = blockIdx.x * 256 + threadIdx.x;   // 0..65535
    const int bh = i >> 9;
    const int m = (i >> 5) & 15;
    g_co[i] = (g_coacc[i] + g_vc[i]) / (g_cnt[bh * 16 + m] + 1.f);
}

// ---------------- out_tok gather ----------------
__global__ void k_ot()
{
    const int bh = blockIdx.x;
    const int t = blockIdx.y * 256 + threadIdx.x;
    __shared__ float co[16][33];
    {
        const int m = threadIdx.x >> 5, d = threadIdx.x & 31;
        co[m][d]     = g_co[bh * 512 + threadIdx.x];
        co[m + 8][d] = g_co[bh * 512 + 256 + threadIdx.x];
    }
    __syncthreads();
    const size_t o = (size_t)bh * T_TOK + t;
    const float w0 = g_w[o * 2 + 0];
    const float w1 = g_w[o * 2 + 1];
    const int sel = g_sel[o];
    const int i0 = sel & 255, i1 = sel >> 8;
    const int b = bh >> 3, h = bh & 7;
    float* dst = g_ot + ((size_t)t * B_SZ + b) * HD + h * HDIM;
#pragma unroll
    for (int d4 = 0; d4 < 8; d4++) {
        float4 r;
        r.x = w0 * co[i0][d4 * 4 + 0] + w1 * co[i1][d4 * 4 + 0];
        r.y = w0 * co[i0][d4 * 4 + 1] + w1 * co[i1][d4 * 4 + 1];
        r.z = w0 * co[i0][d4 * 4 + 2] + w1 * co[i1][d4 * 4 + 2];
        r.w = w0 * co[i0][d4 * 4 + 3] + w1 * co[i1][d4 * 4 + 3];
        *(float4*)(dst + d4 * 4) = r;
    }
}

// ---------------- launch ----------------
extern "C" void kernel_launch(void* const* d_in, const int* in_sizes, int n_in,
                              void* d_out, int out_size)
{
    const float* x      = (const float*)d_in[0];
    const float* f_w    = (const float*)d_in[1];
    const float* f_b    = (const float*)d_in[2];
    const float* v_w    = (const float*)d_in[3];
    const float* v_b    = (const float*)d_in[4];
    const float* proj_w = (const float*)d_in[5];
    const float* proj_b = (const float*)d_in[6];
    const float* alpha  = (const float*)d_in[7];
    const float* beta   = (const float*)d_in[8];
    float* out = (float*)d_out;

    k_zero<<<BH * M_CT * HDIM / 256, 256>>>();
    k_gemm<<<dim3(NROWS / 128, 4), 256>>>(x, f_w, f_b, v_w, v_b, nullptr, 0);
    k_pool<<<BH * M_CT, 256>>>();
    k_sim<<<dim3(BH, T_TOK / 256), 256>>>(alpha, beta);
    k_centers<<<dim3(BH, CSPLIT), 256>>>();
    k_cofin<<<BH * M_CT * HDIM / 256, 256>>>();
    k_ot<<<dim3(BH, T_TOK / 256), 256>>>();
    k_gemm<<<dim3(NROWS / 128, 2), 256>>>(nullptr, proj_w, proj_b, nullptr, nullptr, out, 1);
}

// round 6
// speedup vs baseline: 1.5458x; 1.4414x over previous
#include <cuda_runtime.h>
#include <math.h>
#include <stdint.h>

// R6 = R5 resubmission (R5 bench died to a container/infra failure, not a kernel verdict).
// Split-tf32 (3xMMA) q GEMM + single-tf32 v/proj GEMMs on mma.sync m16n8k8.

// ---------------- problem constants ----------------
#define T_TOK 4096
#define B_SZ  16
#define CIN   256
#define HEADS 8
#define HDIM  32
#define HD    256
#define SIDE  64
#define M_CT  16
#define BH    128
#define NROWS (T_TOK * B_SZ)   // 65536
#define CSPLIT 4

// ---------------- GEMM tiling (mma.sync m16n8k8 tf32) ----------------
#define KC   32                 // K floats per smem chunk
#define NCH  (CIN / KC)         // 8
#define PADK 36                 // padded floats per smem row (bank-conflict-free)
#define TILE_F (128 * PADK)     // floats per tile
#define STAGE2_F (2 * TILE_F)   // A + B           (single-precision path)
#define STAGE4_F (4 * TILE_F)   // Ahi,Alo,Whi,Wlo (split path)
#define DYN_SMEM2 (2 * STAGE2_F * 4)   // 73728 B
#define DYN_SMEM4 (2 * STAGE4_F * 4)   // 147456 B

// ---------------- scratch ----------------
__device__ float g_xhi[(size_t)NROWS * CIN];
__device__ float g_xlo[(size_t)NROWS * CIN];
__device__ float g_whi[512 * CIN];            // f_w rows 0..255, v_w rows 256..511 (tf32 hi)
__device__ float g_wlo[256 * CIN];            // f_w lo
__device__ float g_pc[256 * CIN];             // proj_w tf32 hi
__device__ float g_q[(size_t)BH * T_TOK * HDIM];
__device__ float g_v[(size_t)BH * T_TOK * HDIM];
__device__ float g_chat[BH * M_CT * HDIM];
__device__ float g_vc[BH * M_CT * HDIM];
__device__ float g_co[BH * M_CT * HDIM];
__device__ float g_coacc[BH * M_CT * HDIM];
__device__ float g_cnt[BH * M_CT];
__device__ float g_w[(size_t)BH * T_TOK * 2];
__device__ int   g_sel[(size_t)BH * T_TOK];
__device__ float g_ot[(size_t)NROWS * HD];    // tf32-rounded out_tok [T,B,HD]

// ---------------- helpers ----------------
__device__ __forceinline__ uint32_t smem_u32(const void* p) {
    uint32_t a;
    asm("{ .reg .u64 t; cvta.to.shared.u64 t, %1; cvt.u32.u64 %0, t; }" : "=r"(a) : "l"(p));
    return a;
}
__device__ __forceinline__ void cp16(uint32_t dst, const void* src) {
    asm volatile("cp.async.cg.shared.global [%0], [%1], 16;" :: "r"(dst), "l"(src) : "memory");
}
__device__ __forceinline__ float totf32(float v) {
    uint32_t o;
    asm("cvt.rna.tf32.f32 %0, %1;" : "=r"(o) : "f"(v));
    return __uint_as_float(o);
}
__device__ __forceinline__ void mma_tf32(float* c, const uint32_t* a, const uint32_t* b) {
    asm volatile(
        "mma.sync.aligned.m16n8k8.row.col.f32.tf32.tf32.f32 "
        "{%0,%1,%2,%3},{%4,%5,%6,%7},{%8,%9},{%0,%1,%2,%3};"
        : "+f"(c[0]), "+f"(c[1]), "+f"(c[2]), "+f"(c[3])
        : "r"(a[0]), "r"(a[1]), "r"(a[2]), "r"(a[3]), "r"(b[0]), "r"(b[1]));
}

// one tile (128 rows x 32 floats) from gsrc into padded smem
__device__ __forceinline__ void load_tile(const float* __restrict__ gsrc,
                                          uint32_t sdst, int tid)
{
    const int seg = tid & 7;
    const int r0 = tid >> 3;
#pragma unroll
    for (int i = 0; i < 4; i++) {
        const int r = r0 + i * 32;
        cp16(sdst + (uint32_t)r * (PADK * 4) + seg * 16,
             (const char*)gsrc + (size_t)r * (CIN * 4) + seg * 16);
    }
}

// ---------------- split-tf32 q GEMM (3 MMA terms) ----------------
// q[n, j] = sum_k x[n,k] * f_w[j,k] + f_b[j], j tile = ct*128
__global__ __launch_bounds__(256, 1)
void k_qgemm(const float* __restrict__ f_b)
{
    extern __shared__ float dynf[];
    __shared__ float sbias[128];

    const int tid = threadIdx.x;
    const int wid = tid >> 5;
    const int lane = tid & 31;
    const int group = lane >> 2;
    const int tig = lane & 3;
    const int wm = wid & 1;
    const int wn = wid >> 1;
    const int rowBase = blockIdx.x * 128;
    const int ct = blockIdx.y;

    if (tid < 128) sbias[tid] = f_b[ct * 128 + tid];

    const uint32_t sbase = smem_u32(dynf);
    const float* Ahi = g_xhi + (size_t)rowBase * CIN;
    const float* Alo = g_xlo + (size_t)rowBase * CIN;
    const float* Whi = g_whi + (size_t)(ct * 128) * CIN;
    const float* Wlo = g_wlo + (size_t)(ct * 128) * CIN;

    float acc[4][4][4];
#pragma unroll
    for (int mi = 0; mi < 4; mi++)
#pragma unroll
        for (int ni = 0; ni < 4; ni++)
#pragma unroll
            for (int r = 0; r < 4; r++) acc[mi][ni][r] = 0.f;

    // prefetch 2 chunks (4 tiles each)
#pragma unroll
    for (int p = 0; p < 2; p++) {
        const uint32_t sb = sbase + p * STAGE4_F * 4;
        load_tile(Ahi + p * KC, sb, tid);
        load_tile(Alo + p * KC, sb + TILE_F * 4, tid);
        load_tile(Whi + p * KC, sb + 2 * TILE_F * 4, tid);
        load_tile(Wlo + p * KC, sb + 3 * TILE_F * 4, tid);
        asm volatile("cp.async.commit_group;" ::: "memory");
    }

#pragma unroll 1
    for (int c = 0; c < NCH; c++) {
        const int s = c & 1;
        const float* sAhi = dynf + s * STAGE4_F;
        const float* sAlo = sAhi + TILE_F;
        const float* sWhi = sAlo + TILE_F;
        const float* sWlo = sWhi + TILE_F;
        if (c < NCH - 2) asm volatile("cp.async.wait_group 1;" ::: "memory");
        else             asm volatile("cp.async.wait_group 0;" ::: "memory");
        __syncthreads();
#pragma unroll
        for (int kk8 = 0; kk8 < 4; kk8++) {
            const int kk = kk8 * 8;
            uint32_t ah[4][4], al[4][4], bh[4][2], bl[4][2];
#pragma unroll
            for (int mi = 0; mi < 4; mi++) {
                const int r0 = wm * 64 + mi * 16 + group;
                ah[mi][0] = __float_as_uint(sAhi[r0 * PADK + kk + tig]);
                ah[mi][1] = __float_as_uint(sAhi[(r0 + 8) * PADK + kk + tig]);
                ah[mi][2] = __float_as_uint(sAhi[r0 * PADK + kk + tig + 4]);
                ah[mi][3] = __float_as_uint(sAhi[(r0 + 8) * PADK + kk + tig + 4]);
                al[mi][0] = __float_as_uint(sAlo[r0 * PADK + kk + tig]);
                al[mi][1] = __float_as_uint(sAlo[(r0 + 8) * PADK + kk + tig]);
                al[mi][2] = __float_as_uint(sAlo[r0 * PADK + kk + tig + 4]);
                al[mi][3] = __float_as_uint(sAlo[(r0 + 8) * PADK + kk + tig + 4]);
            }
#pragma unroll
            for (int ni = 0; ni < 4; ni++) {
                const int cb = wn * 32 + ni * 8 + group;
                bh[ni][0] = __float_as_uint(sWhi[cb * PADK + kk + tig]);
                bh[ni][1] = __float_as_uint(sWhi[cb * PADK + kk + tig + 4]);
                bl[ni][0] = __float_as_uint(sWlo[cb * PADK + kk + tig]);
                bl[ni][1] = __float_as_uint(sWlo[cb * PADK + kk + tig + 4]);
            }
#pragma unroll
            for (int mi = 0; mi < 4; mi++)
#pragma unroll
                for (int ni = 0; ni < 4; ni++) {
                    mma_tf32(acc[mi][ni], al[mi], bh[ni]);
                    mma_tf32(acc[mi][ni], ah[mi], bl[ni]);
                    mma_tf32(acc[mi][ni], ah[mi], bh[ni]);
                }
        }
        __syncthreads();
        if (c + 2 < NCH) {
            const uint32_t sb = sbase + s * STAGE4_F * 4;
            load_tile(Ahi + (c + 2) * KC, sb, tid);
            load_tile(Alo + (c + 2) * KC, sb + TILE_F * 4, tid);
            load_tile(Whi + (c + 2) * KC, sb + 2 * TILE_F * 4, tid);
            load_tile(Wlo + (c + 2) * KC, sb + 3 * TILE_F * 4, tid);
            asm volatile("cp.async.commit_group;" ::: "memory");
        }
    }

    // epilogue: scatter into g_q [B][H][T][D]
#pragma unroll
    for (int mi = 0; mi < 4; mi++)
#pragma unroll
        for (int ni = 0; ni < 4; ni++) {
            const int row_l = wm * 64 + mi * 16 + group;
            const int col_l = wn * 32 + ni * 8 + 2 * tig;
            const float bx = sbias[col_l], by = sbias[col_l + 1];
#pragma unroll
            for (int h2 = 0; h2 < 2; h2++) {
                const int n_g = rowBase + row_l + h2 * 8;
                float2 val;
                val.x = acc[mi][ni][h2 * 2 + 0] + bx;
                val.y = acc[mi][ni][h2 * 2 + 1] + by;
                const int t = n_g >> 4, bb = n_g & 15;
                const int cLoc = ct * 128 + col_l;
                const int h = cLoc >> 5, d = cLoc & 31;
                *(float2*)(g_q + (((size_t)bb * HEADS + h) * T_TOK + t) * HDIM + d) = val;
            }
        }
}

// ---------------- single tf32 GEMM (v / proj) ----------------
// mode 0: A=g_xhi, W=g_whi rows 256+ct*128 (v weights), scatter into g_v
// mode 1: A=g_ot, W=g_pc rows ct*128, plain row-major into outp
__global__ __launch_bounds__(256, 2)
void k_mgemm(const float* __restrict__ biasPtr, float* __restrict__ outp, int mode)
{
    extern __shared__ float dynf[];
    __shared__ float sbias[128];

    const int tid = threadIdx.x;
    const int wid = tid >> 5;
    const int lane = tid & 31;
    const int group = lane >> 2;
    const int tig = lane & 3;
    const int wm = wid & 1;
    const int wn = wid >> 1;
    const int rowBase = blockIdx.x * 128;
    const int ct = blockIdx.y;

    const float* A = mode ? g_ot : g_xhi;
    const float* W = mode ? (g_pc + (size_t)(ct * 128) * CIN)
                          : (g_whi + (size_t)(256 + ct * 128) * CIN);
    if (tid < 128) sbias[tid] = biasPtr[ct * 128 + tid];

    const uint32_t sbase = smem_u32(dynf);
    const float* Ab = A + (size_t)rowBase * CIN;

    float acc[4][4][4];
#pragma unroll
    for (int mi = 0; mi < 4; mi++)
#pragma unroll
        for (int ni = 0; ni < 4; ni++)
#pragma unroll
            for (int r = 0; r < 4; r++) acc[mi][ni][r] = 0.f;

#pragma unroll
    for (int p = 0; p < 2; p++) {
        const uint32_t sb = sbase + p * STAGE2_F * 4;
        load_tile(Ab + p * KC, sb, tid);
        load_tile(W + p * KC, sb + TILE_F * 4, tid);
        asm volatile("cp.async.commit_group;" ::: "memory");
    }

#pragma unroll 1
    for (int c = 0; c < NCH; c++) {
        const int s = c & 1;
        const float* As = dynf + s * STAGE2_F;
        const float* Bs = As + TILE_F;
        if (c < NCH - 2) asm volatile("cp.async.wait_group 1;" ::: "memory");
        else             asm volatile("cp.async.wait_group 0;" ::: "memory");
        __syncthreads();
#pragma unroll
        for (int kk8 = 0; kk8 < 4; kk8++) {
            const int kk = kk8 * 8;
            uint32_t a[4][4], b[4][2];
#pragma unroll
            for (int mi = 0; mi < 4; mi++) {
                const int r0 = wm * 64 + mi * 16 + group;
                a[mi][0] = __float_as_uint(As[r0 * PADK + kk + tig]);
                a[mi][1] = __float_as_uint(As[(r0 + 8) * PADK + kk + tig]);
                a[mi][2] = __float_as_uint(As[r0 * PADK + kk + tig + 4]);
                a[mi][3] = __float_as_uint(As[(r0 + 8) * PADK + kk + tig + 4]);
            }
#pragma unroll
            for (int ni = 0; ni < 4; ni++) {
                const int cb = wn * 32 + ni * 8 + group;
                b[ni][0] = __float_as_uint(Bs[cb * PADK + kk + tig]);
                b[ni][1] = __float_as_uint(Bs[cb * PADK + kk + tig + 4]);
            }
#pragma unroll
            for (int mi = 0; mi < 4; mi++)
#pragma unroll
                for (int ni = 0; ni < 4; ni++)
                    mma_tf32(acc[mi][ni], a[mi], b[ni]);
        }
        __syncthreads();
        if (c + 2 < NCH) {
            const uint32_t sb = sbase + s * STAGE2_F * 4;
            load_tile(Ab + (c + 2) * KC, sb, tid);
            load_tile(W + (c + 2) * KC, sb + TILE_F * 4, tid);
            asm volatile("cp.async.commit_group;" ::: "memory");
        }
    }

#pragma unroll
    for (int mi = 0; mi < 4; mi++)
#pragma unroll
        for (int ni = 0; ni < 4; ni++) {
            const int row_l = wm * 64 + mi * 16 + group;
            const int col_l = wn * 32 + ni * 8 + 2 * tig;
            const float bx = sbias[col_l], by = sbias[col_l + 1];
#pragma unroll
            for (int h2 = 0; h2 < 2; h2++) {
                const int n_g = rowBase + row_l + h2 * 8;
                float2 val;
                val.x = acc[mi][ni][h2 * 2 + 0] + bx;
                val.y = acc[mi][ni][h2 * 2 + 1] + by;
                if (mode == 1) {
                    *(float2*)(outp + (size_t)n_g * HD + ct * 128 + col_l) = val;
                } else {
                    const int t = n_g >> 4, bb = n_g & 15;
                    const int cLoc = ct * 128 + col_l;
                    const int h = cLoc >> 5, d = cLoc & 31;
                    *(float2*)(g_v + (((size_t)bb * HEADS + h) * T_TOK + t) * HDIM + d) = val;
                }
            }
        }
}

// ---------------- hi/lo conversion ----------------
__global__ void k_cvtx(const float4* __restrict__ x)
{
    const int i = blockIdx.x * 256 + threadIdx.x;
    float4 v = x[i], h, l;
    h.x = totf32(v.x); l.x = totf32(v.x - h.x);
    h.y = totf32(v.y); l.y = totf32(v.y - h.y);
    h.z = totf32(v.z); l.z = totf32(v.z - h.z);
    h.w = totf32(v.w); l.w = totf32(v.w - h.w);
    ((float4*)g_xhi)[i] = h;
    ((float4*)g_xlo)[i] = l;
}

__global__ void k_cvtw(const float4* __restrict__ fw, const float4* __restrict__ vw,
                       const float4* __restrict__ pw)
{
    const int i = blockIdx.x * 256 + threadIdx.x;  // 0..49151
    float4 v;
    if (i < 16384)       v = fw[i];
    else if (i < 32768)  v = vw[i - 16384];
    else                 v = pw[i - 32768];
    float4 h, l;
    h.x = totf32(v.x); l.x = totf32(v.x - h.x);
    h.y = totf32(v.y); l.y = totf32(v.y - h.y);
    h.z = totf32(v.z); l.z = totf32(v.z - h.z);
    h.w = totf32(v.w); l.w = totf32(v.w - h.w);
    if (i < 16384)      { ((float4*)g_whi)[i] = h; ((float4*)g_wlo)[i] = l; }
    else if (i < 32768)   ((float4*)g_whi)[i] = h;
    else                  ((float4*)g_pc)[i - 32768] = h;
}

// ---------------- zero accumulators ----------------
__global__ void k_zero()
{
    const int i = blockIdx.x * 256 + threadIdx.x;
    g_coacc[i] = 0.f;
    if (i < BH * M_CT) g_cnt[i] = 0.f;
}

// ---------------- pooling ----------------
__global__ void k_pool()
{
    const int bh = blockIdx.x >> 4;
    const int m  = blockIdx.x & 15;
    const int py = m >> 2, px = m & 3;
    const int ti = threadIdx.x >> 5;
    const int d  = threadIdx.x & 31;

    float sq = 0.f, sv = 0.f;
    for (int j = ti; j < 256; j += 8) {
        const int yi = j >> 4, xi = j & 15;
        const int t = (py * 16 + yi) * SIDE + px * 16 + xi;
        const size_t off = ((size_t)bh * T_TOK + t) * HDIM + d;
        sq += g_q[off];
        sv += g_v[off];
    }
    __shared__ float shq[8][32], shv[8][32];
    shq[ti][d] = sq; shv[ti][d] = sv;
    __syncthreads();
    if (threadIdx.x < 32) {
        const int dd = threadIdx.x;
        float aq = 0.f, av = 0.f;
#pragma unroll
        for (int i = 0; i < 8; i++) { aq += shq[i][dd]; av += shv[i][dd]; }
        aq *= (1.f / 256.f); av *= (1.f / 256.f);
        float nn = aq * aq;
#pragma unroll
        for (int o = 16; o; o >>= 1) nn += __shfl_xor_sync(0xffffffffu, nn, o);
        const float denom = fmaxf(sqrtf(nn), 1e-12f);
        g_chat[bh * (M_CT * HDIM) + m * HDIM + dd] = aq / denom;
        g_vc[bh * (M_CT * HDIM) + m * HDIM + dd] = av;
    }
}

// ---------------- similarity + top-2 ----------------
__global__ void k_sim(const float* __restrict__ alpha, const float* __restrict__ beta)
{
    const int bh = blockIdx.x;
    const int t = blockIdx.y * 256 + threadIdx.x;
    __shared__ float ch[M_CT * HDIM];
    ch[threadIdx.x] = g_chat[bh * 512 + threadIdx.x];
    ch[256 + threadIdx.x] = g_chat[bh * 512 + 256 + threadIdx.x];
    __syncthreads();

    float q[32];
    const float* qp = g_q + ((size_t)bh * T_TOK + t) * HDIM;
#pragma unroll
    for (int i = 0; i < 8; i++) {
        float4 v4 = *(const float4*)(qp + i * 4);
        q[i * 4 + 0] = v4.x; q[i * 4 + 1] = v4.y; q[i * 4 + 2] = v4.z; q[i * 4 + 3] = v4.w;
    }
    float qn = 0.f;
#pragma unroll
    for (int d = 0; d < 32; d++) qn += q[d] * q[d];
    const float rq = 1.f / fmaxf(sqrtf(qn), 1e-12f);
    const float a = alpha[0], b = beta[0];

    float s[16];
#pragma unroll
    for (int m = 0; m < 16; m++) {
        float dot = 0.f;
#pragma unroll
        for (int d = 0; d < 32; d++) dot = fmaf(ch[m * 32 + d], q[d], dot);
        const float z = b + a * (dot * rq);
        s[m] = 1.f / (1.f + expf(-z));
    }
    int i0 = 0; float v0 = s[0];
#pragma unroll
    for (int m = 1; m < 16; m++) if (s[m] > v0) { v0 = s[m]; i0 = m; }
    int i1 = -1; float v1 = -1.f;
#pragma unroll
    for (int m = 0; m < 16; m++) if (m != i0 && s[m] > v1) { v1 = s[m]; i1 = m; }

    const float p0 = v0 * v0, p1 = v1 * v1;
    const float inv = 1.f / (p0 + p1 + 1e-6f);
    const size_t o = (size_t)bh * T_TOK + t;
    g_w[o * 2 + 0] = p0 * inv;
    g_w[o * 2 + 1] = p1 * inv;
    g_sel[o] = i0 | (i1 << 8);
}

// ---------------- centers_out partial sums ----------------
__global__ __launch_bounds__(256)
void k_centers()
{
    const int bh = blockIdx.x;
    const int tBase = blockIdx.y * (T_TOK / CSPLIT);
    const int wi = threadIdx.x >> 5, lane = threadIdx.x & 31;

    float acc[16], wacc[16];
#pragma unroll
    for (int m = 0; m < 16; m++) { acc[m] = 0.f; wacc[m] = 0.f; }

#pragma unroll 2
    for (int t = tBase + wi; t < tBase + T_TOK / CSPLIT; t += 8) {
        const size_t o = (size_t)bh * T_TOK + t;
        const float vv = g_v[o * HDIM + lane];
        const float2 w01 = *(const float2*)(g_w + o * 2);
        const int sel = g_sel[o];
        const int i0 = sel & 255, i1 = sel >> 8;
#pragma unroll
        for (int m = 0; m < 16; m++) {
            const float w = (m == i0) ? w01.x : ((m == i1) ? w01.y : 0.f);
            acc[m] = fmaf(w, vv, acc[m]);
            wacc[m] += w;
        }
    }

    __shared__ float sacc[8][16][32];
    __shared__ float swacc[8][16];
#pragma unroll
    for (int m = 0; m < 16; m++) sacc[wi][m][lane] = acc[m];
    if (lane == 0) {
#pragma unroll
        for (int m = 0; m < 16; m++) swacc[wi][m] = wacc[m];
    }
    __syncthreads();

    for (int i = threadIdx.x; i < 512; i += 256) {
        const int m = i >> 5, d = i & 31;
        float s = 0.f;
#pragma unroll
        for (int w = 0; w < 8; w++) s += sacc[w][m][d];
        atomicAdd(&g_coacc[bh * 512 + i], s);
    }
    if (threadIdx.x < 16) {
        float s = 0.f;
#pragma unroll
        for (int w = 0; w < 8; w++) s += swacc[w][threadIdx.x];
        atomicAdd(&g_cnt[bh * 16 + threadIdx.x], s);
    }
}

// ---------------- finalize centers_out ----------------
__global__ void k_cofin()
{
    const int i = blockIdx.x * 256 + threadIdx.x;
    const int bh = i >> 9;
    const int m = (i >> 5) & 15;
    g_co[i] = (g_coacc[i] + g_vc[i]) / (g_cnt[bh * 16 + m] + 1.f);
}

// ---------------- out_tok gather (tf32-rounded for the proj GEMM) ----------------
__global__ void k_ot()
{
    const int bh = blockIdx.x;
    const int t = blockIdx.y * 256 + threadIdx.x;
    __shared__ float co[16][33];
    {
        const int m = threadIdx.x >> 5, d = threadIdx.x & 31;
        co[m][d]     = g_co[bh * 512 + threadIdx.x];
        co[m + 8][d] = g_co[bh * 512 + 256 + threadIdx.x];
    }
    __syncthreads();
    const size_t o = (size_t)bh * T_TOK + t;
    const float w0 = g_w[o * 2 + 0];
    const float w1 = g_w[o * 2 + 1];
    const int sel = g_sel[o];
    const int i0 = sel & 255, i1 = sel >> 8;
    const int b = bh >> 3, h = bh & 7;
    float* dst = g_ot + ((size_t)t * B_SZ + b) * HD + h * HDIM;
#pragma unroll
    for (int d4 = 0; d4 < 8; d4++) {
        float4 r;
        r.x = totf32(w0 * co[i0][d4 * 4 + 0] + w1 * co[i1][d4 * 4 + 0]);
        r.y = totf32(w0 * co[i0][d4 * 4 + 1] + w1 * co[i1][d4 * 4 + 1]);
        r.z = totf32(w0 * co[i0][d4 * 4 + 2] + w1 * co[i1][d4 * 4 + 2]);
        r.w = totf32(w0 * co[i0][d4 * 4 + 3] + w1 * co[i1][d4 * 4 + 3]);
        *(float4*)(dst + d4 * 4) = r;
    }
}

// ---------------- launch ----------------
extern "C" void kernel_launch(void* const* d_in, const int* in_sizes, int n_in,
                              void* d_out, int out_size)
{
    const float* x      = (const float*)d_in[0];
    const float* f_w    = (const float*)d_in[1];
    const float* f_b    = (const float*)d_in[2];
    const float* v_w    = (const float*)d_in[3];
    const float* v_b    = (const float*)d_in[4];
    const float* proj_w = (const float*)d_in[5];
    const float* proj_b = (const float*)d_in[6];
    const float* alpha  = (const float*)d_in[7];
    const float* beta   = (const float*)d_in[8];
    float* out = (float*)d_out;

    cudaFuncSetAttribute(k_qgemm, cudaFuncAttributeMaxDynamicSharedMemorySize, DYN_SMEM4);
    cudaFuncSetAttribute(k_mgemm, cudaFuncAttributeMaxDynamicSharedMemorySize, DYN_SMEM2);

    k_cvtx<<<NROWS * CIN / 1024, 256>>>((const float4*)x);
    k_cvtw<<<192, 256>>>((const float4*)f_w, (const float4*)v_w, (const float4*)proj_w);
    k_zero<<<BH * M_CT * HDIM / 256, 256>>>();
    k_qgemm<<<dim3(NROWS / 128, 2), 256, DYN_SMEM4>>>(f_b);
    k_mgemm<<<dim3(NROWS / 128, 2), 256, DYN_SMEM2>>>(v_b, nullptr, 0);
    k_pool<<<BH * M_CT, 256>>>();
    k_sim<<<dim3(BH, T_TOK / 256), 256>>>(alpha, beta);
    k_centers<<<dim3(BH, CSPLIT), 256>>>();
    k_cofin<<<BH * M_CT * HDIM / 256, 256>>>();
    k_ot<<<dim3(BH, T_TOK / 256), 256>>>();
    k_mgemm<<<dim3(NROWS / 128, 2), 256, DYN_SMEM2>>>(proj_b, out, 1);
}

// round 11
// speedup vs baseline: 1.7115x; 1.1072x over previous
#include <cuda_runtime.h>
#include <math.h>
#include <stdint.h>

// R10 = R8 resubmission (two broker "container failed twice" verdicts with no
// kernel-attributable error; R5->R6 showed identical resubmission succeeds).
// Fused tf32 conversion in fragment loads; 72KB smem -> 2 CTAs/SM; in-kernel
// g_ot selection via mode flag.

// ---------------- problem constants ----------------
#define T_TOK 4096
#define B_SZ  16
#define CIN   256
#define HEADS 8
#define HDIM  32
#define HD    256
#define SIDE  64
#define M_CT  16
#define BH    128
#define NROWS (T_TOK * B_SZ)   // 65536
#define CSPLIT 4

// ---------------- GEMM tiling (mma.sync m16n8k8 tf32) ----------------
#define KC   32                 // K floats per smem chunk
#define NCH  (CIN / KC)         // 8
#define PADK 36                 // padded floats per smem row
#define TILE_F (128 * PADK)
#define STAGE_F (2 * TILE_F)    // raw A + raw W
#define DYN_SMEM (2 * STAGE_F * 4)   // 73728 B (double buffered)

// ---------------- scratch ----------------
__device__ float g_q[(size_t)BH * T_TOK * HDIM];
__device__ float g_v[(size_t)BH * T_TOK * HDIM];
__device__ float g_chat[BH * M_CT * HDIM];
__device__ float g_vc[BH * M_CT * HDIM];
__device__ float g_co[BH * M_CT * HDIM];
__device__ float g_coacc[BH * M_CT * HDIM];
__device__ float g_cnt[BH * M_CT];
__device__ float g_w[(size_t)BH * T_TOK * 2];
__device__ int   g_sel[(size_t)BH * T_TOK];
__device__ float g_ot[(size_t)NROWS * HD];    // out_tok [T,B,HD] (raw fp32)

// ---------------- helpers ----------------
__device__ __forceinline__ uint32_t smem_u32(const void* p) {
    uint32_t a;
    asm("{ .reg .u64 t; cvta.to.shared.u64 t, %1; cvt.u32.u64 %0, t; }" : "=r"(a) : "l"(p));
    return a;
}
__device__ __forceinline__ void cp16(uint32_t dst, const void* src) {
    asm volatile("cp.async.cg.shared.global [%0], [%1], 16;" :: "r"(dst), "l"(src) : "memory");
}
__device__ __forceinline__ float totf32(float v) {
    uint32_t o;
    asm("cvt.rna.tf32.f32 %0, %1;" : "=r"(o) : "f"(v));
    return __uint_as_float(o);
}
__device__ __forceinline__ void mma_tf32(float* c, const uint32_t* a, const uint32_t* b) {
    asm volatile(
        "mma.sync.aligned.m16n8k8.row.col.f32.tf32.tf32.f32 "
        "{%0,%1,%2,%3},{%4,%5,%6,%7},{%8,%9},{%0,%1,%2,%3};"
        : "+f"(c[0]), "+f"(c[1]), "+f"(c[2]), "+f"(c[3])
        : "r"(a[0]), "r"(a[1]), "r"(a[2]), "r"(a[3]), "r"(b[0]), "r"(b[1]));
}

// one tile (128 rows x 32 floats) raw copy into padded smem
__device__ __forceinline__ void load_tile(const float* __restrict__ gsrc,
                                          uint32_t sdst, int tid)
{
    const int seg = tid & 7;
    const int r0 = tid >> 3;
#pragma unroll
    for (int i = 0; i < 4; i++) {
        const int r = r0 + i * 32;
        cp16(sdst + (uint32_t)r * (PADK * 4) + seg * 16,
             (const char*)gsrc + (size_t)r * (CIN * 4) + seg * 16);
    }
}

// ---------------- split-tf32 q GEMM (3 MMA terms, fused hi/lo) ----------------
// q[n, j] = sum_k x[n,k] * f_w[j,k] + f_b[j], col tile = ct*128
__global__ __launch_bounds__(256, 2)
void k_qgemm(const float* __restrict__ x, const float* __restrict__ f_w,
             const float* __restrict__ f_b)
{
    extern __shared__ float dynf[];
    __shared__ float sbias[128];

    const int tid = threadIdx.x;
    const int wid = tid >> 5;
    const int lane = tid & 31;
    const int group = lane >> 2;
    const int tig = lane & 3;
    const int wm = wid & 1;
    const int wn = wid >> 1;
    const int rowBase = blockIdx.x * 128;
    const int ct = blockIdx.y;

    if (tid < 128) sbias[tid] = f_b[ct * 128 + tid];

    const uint32_t sbase = smem_u32(dynf);
    const float* A = x + (size_t)rowBase * CIN;
    const float* W = f_w + (size_t)(ct * 128) * CIN;

    float acc[4][4][4];
#pragma unroll
    for (int mi = 0; mi < 4; mi++)
#pragma unroll
        for (int ni = 0; ni < 4; ni++)
#pragma unroll
            for (int r = 0; r < 4; r++) acc[mi][ni][r] = 0.f;

#pragma unroll
    for (int p = 0; p < 2; p++) {
        const uint32_t sb = sbase + p * STAGE_F * 4;
        load_tile(A + p * KC, sb, tid);
        load_tile(W + p * KC, sb + TILE_F * 4, tid);
        asm volatile("cp.async.commit_group;" ::: "memory");
    }

#pragma unroll 1
    for (int c = 0; c < NCH; c++) {
        const int s = c & 1;
        const float* As = dynf + s * STAGE_F;
        const float* Bs = As + TILE_F;
        if (c < NCH - 2) asm volatile("cp.async.wait_group 1;" ::: "memory");
        else             asm volatile("cp.async.wait_group 0;" ::: "memory");
        __syncthreads();
#pragma unroll
        for (int kk8 = 0; kk8 < 4; kk8++) {
            const int kk = kk8 * 8;
            uint32_t ah[4][4], al[4][4], bh[4][2], bl[4][2];
#pragma unroll
            for (int mi = 0; mi < 4; mi++) {
                const int r0 = wm * 64 + mi * 16 + group;
                float raw[4];
                raw[0] = As[r0 * PADK + kk + tig];
                raw[1] = As[(r0 + 8) * PADK + kk + tig];
                raw[2] = As[r0 * PADK + kk + tig + 4];
                raw[3] = As[(r0 + 8) * PADK + kk + tig + 4];
#pragma unroll
                for (int r = 0; r < 4; r++) {
                    const float h = totf32(raw[r]);
                    ah[mi][r] = __float_as_uint(h);
                    al[mi][r] = __float_as_uint(totf32(raw[r] - h));
                }
            }
#pragma unroll
            for (int ni = 0; ni < 4; ni++) {
                const int cb = wn * 32 + ni * 8 + group;
                float raw[2];
                raw[0] = Bs[cb * PADK + kk + tig];
                raw[1] = Bs[cb * PADK + kk + tig + 4];
#pragma unroll
                for (int r = 0; r < 2; r++) {
                    const float h = totf32(raw[r]);
                    bh[ni][r] = __float_as_uint(h);
                    bl[ni][r] = __float_as_uint(totf32(raw[r] - h));
                }
            }
#pragma unroll
            for (int mi = 0; mi < 4; mi++)
#pragma unroll
                for (int ni = 0; ni < 4; ni++) {
                    mma_tf32(acc[mi][ni], al[mi], bh[ni]);
                    mma_tf32(acc[mi][ni], ah[mi], bl[ni]);
                    mma_tf32(acc[mi][ni], ah[mi], bh[ni]);
                }
        }
        __syncthreads();
        if (c + 2 < NCH) {
            const uint32_t sb = sbase + s * STAGE_F * 4;
            load_tile(A + (c + 2) * KC, sb, tid);
            load_tile(W + (c + 2) * KC, sb + TILE_F * 4, tid);
            asm volatile("cp.async.commit_group;" ::: "memory");
        }
    }

    // epilogue: scatter into g_q [B][H][T][D]
#pragma unroll
    for (int mi = 0; mi < 4; mi++)
#pragma unroll
        for (int ni = 0; ni < 4; ni++) {
            const int row_l = wm * 64 + mi * 16 + group;
            const int col_l = wn * 32 + ni * 8 + 2 * tig;
            const float bx = sbias[col_l], by = sbias[col_l + 1];
#pragma unroll
            for (int h2 = 0; h2 < 2; h2++) {
                const int n_g = rowBase + row_l + h2 * 8;
                float2 val;
                val.x = acc[mi][ni][h2 * 2 + 0] + bx;
                val.y = acc[mi][ni][h2 * 2 + 1] + by;
                const int t = n_g >> 4, bb = n_g & 15;
                const int cLoc = ct * 128 + col_l;
                const int h = cLoc >> 5, d = cLoc & 31;
                *(float2*)(g_q + (((size_t)bb * HEADS + h) * T_TOK + t) * HDIM + d) = val;
            }
        }
}

// ---------------- single tf32 GEMM (v / proj), fused hi conversion ----------------
// mode 0: A=Ain(x), W=v_w rows ct*128, scatter into g_v
// mode 1: A=g_ot (selected in-kernel), W=proj_w rows ct*128, row-major into outp
__global__ __launch_bounds__(256, 2)
void k_mgemm(const float* __restrict__ Ain, const float* __restrict__ Win,
             const float* __restrict__ biasPtr, float* __restrict__ outp, int mode)
{
    extern __shared__ float dynf[];
    __shared__ float sbias[128];

    const int tid = threadIdx.x;
    const int wid = tid >> 5;
    const int lane = tid & 31;
    const int group = lane >> 2;
    const int tig = lane & 3;
    const int wm = wid & 1;
    const int wn = wid >> 1;
    const int rowBase = blockIdx.x * 128;
    const int ct = blockIdx.y;

    if (tid < 128) sbias[tid] = biasPtr[ct * 128 + tid];

    const uint32_t sbase = smem_u32(dynf);
    const float* Asel = (mode == 1) ? g_ot : Ain;   // device-side symbol resolution
    const float* A = Asel + (size_t)rowBase * CIN;
    const float* W = Win + (size_t)(ct * 128) * CIN;

    float acc[4][4][4];
#pragma unroll
    for (int mi = 0; mi < 4; mi++)
#pragma unroll
        for (int ni = 0; ni < 4; ni++)
#pragma unroll
            for (int r = 0; r < 4; r++) acc[mi][ni][r] = 0.f;

#pragma unroll
    for (int p = 0; p < 2; p++) {
        const uint32_t sb = sbase + p * STAGE_F * 4;
        load_tile(A + p * KC, sb, tid);
        load_tile(W + p * KC, sb + TILE_F * 4, tid);
        asm volatile("cp.async.commit_group;" ::: "memory");
    }

#pragma unroll 1
    for (int c = 0; c < NCH; c++) {
        const int s = c & 1;
        const float* As = dynf + s * STAGE_F;
        const float* Bs = As + TILE_F;
        if (c < NCH - 2) asm volatile("cp.async.wait_group 1;" ::: "memory");
        else             asm volatile("cp.async.wait_group 0;" ::: "memory");
        __syncthreads();
#pragma unroll
        for (int kk8 = 0; kk8 < 4; kk8++) {
            const int kk = kk8 * 8;
            uint32_t a[4][4], b[4][2];
#pragma unroll
            for (int mi = 0; mi < 4; mi++) {
                const int r0 = wm * 64 + mi * 16 + group;
                a[mi][0] = __float_as_uint(totf32(As[r0 * PADK + kk + tig]));
                a[mi][1] = __float_as_uint(totf32(As[(r0 + 8) * PADK + kk + tig]));
                a[mi][2] = __float_as_uint(totf32(As[r0 * PADK + kk + tig + 4]));
                a[mi][3] = __float_as_uint(totf32(As[(r0 + 8) * PADK + kk + tig + 4]));
            }
#pragma unroll
            for (int ni = 0; ni < 4; ni++) {
                const int cb = wn * 32 + ni * 8 + group;
                b[ni][0] = __float_as_uint(totf32(Bs[cb * PADK + kk + tig]));
                b[ni][1] = __float_as_uint(totf32(Bs[cb * PADK + kk + tig + 4]));
            }
#pragma unroll
            for (int mi = 0; mi < 4; mi++)
#pragma unroll
                for (int ni = 0; ni < 4; ni++)
                    mma_tf32(acc[mi][ni], a[mi], b[ni]);
        }
        __syncthreads();
        if (c + 2 < NCH) {
            const uint32_t sb = sbase + s * STAGE_F * 4;
            load_tile(A + (c + 2) * KC, sb, tid);
            load_tile(W + (c + 2) * KC, sb + TILE_F * 4, tid);
            asm volatile("cp.async.commit_group;" ::: "memory");
        }
    }

#pragma unroll
    for (int mi = 0; mi < 4; mi++)
#pragma unroll
        for (int ni = 0; ni < 4; ni++) {
            const int row_l = wm * 64 + mi * 16 + group;
            const int col_l = wn * 32 + ni * 8 + 2 * tig;
            const float bx = sbias[col_l], by = sbias[col_l + 1];
#pragma unroll
            for (int h2 = 0; h2 < 2; h2++) {
                const int n_g = rowBase + row_l + h2 * 8;
                float2 val;
                val.x = acc[mi][ni][h2 * 2 + 0] + bx;
                val.y = acc[mi][ni][h2 * 2 + 1] + by;
                if (mode == 1) {
                    *(float2*)(outp + (size_t)n_g * HD + ct * 128 + col_l) = val;
                } else {
                    const int t = n_g >> 4, bb = n_g & 15;
                    const int cLoc = ct * 128 + col_l;
                    const int h = cLoc >> 5, d = cLoc & 31;
                    *(float2*)(g_v + (((size_t)bb * HEADS + h) * T_TOK + t) * HDIM + d) = val;
                }
            }
        }
}

// ---------------- zero accumulators ----------------
__global__ void k_zero()
{
    const int i = blockIdx.x * 256 + threadIdx.x;
    g_coacc[i] = 0.f;
    if (i < BH * M_CT) g_cnt[i] = 0.f;
}

// ---------------- pooling ----------------
__global__ void k_pool()
{
    const int bh = blockIdx.x >> 4;
    const int m  = blockIdx.x & 15;
    const int py = m >> 2, px = m & 3;
    const int ti = threadIdx.x >> 5;
    const int d  = threadIdx.x & 31;

    float sq = 0.f, sv = 0.f;
    for (int j = ti; j < 256; j += 8) {
        const int yi = j >> 4, xi = j & 15;
        const int t = (py * 16 + yi) * SIDE + px * 16 + xi;
        const size_t off = ((size_t)bh * T_TOK + t) * HDIM + d;
        sq += g_q[off];
        sv += g_v[off];
    }
    __shared__ float shq[8][32], shv[8][32];
    shq[ti][d] = sq; shv[ti][d] = sv;
    __syncthreads();
    if (threadIdx.x < 32) {
        const int dd = threadIdx.x;
        float aq = 0.f, av = 0.f;
#pragma unroll
        for (int i = 0; i < 8; i++) { aq += shq[i][dd]; av += shv[i][dd]; }
        aq *= (1.f / 256.f); av *= (1.f / 256.f);
        float nn = aq * aq;
#pragma unroll
        for (int o = 16; o; o >>= 1) nn += __shfl_xor_sync(0xffffffffu, nn, o);
        const float denom = fmaxf(sqrtf(nn), 1e-12f);
        g_chat[bh * (M_CT * HDIM) + m * HDIM + dd] = aq / denom;
        g_vc[bh * (M_CT * HDIM) + m * HDIM + dd] = av;
    }
}

// ---------------- similarity + top-2 ----------------
__global__ void k_sim(const float* __restrict__ alpha, const float* __restrict__ beta)
{
    const int bh = blockIdx.x;
    const int t = blockIdx.y * 256 + threadIdx.x;
    __shared__ float ch[M_CT * HDIM];
    ch[threadIdx.x] = g_chat[bh * 512 + threadIdx.x];
    ch[256 + threadIdx.x] = g_chat[bh * 512 + 256 + threadIdx.x];
    __syncthreads();

    float q[32];
    const float* qp = g_q + ((size_t)bh * T_TOK + t) * HDIM;
#pragma unroll
    for (int i = 0; i < 8; i++) {
        float4 v4 = *(const float4*)(qp + i * 4);
        q[i * 4 + 0] = v4.x; q[i * 4 + 1] = v4.y; q[i * 4 + 2] = v4.z; q[i * 4 + 3] = v4.w;
    }
    float qn = 0.f;
#pragma unroll
    for (int d = 0; d < 32; d++) qn += q[d] * q[d];
    const float rq = 1.f / fmaxf(sqrtf(qn), 1e-12f);
    const float a = alpha[0], b = beta[0];

    float s[16];
#pragma unroll
    for (int m = 0; m < 16; m++) {
        float dot = 0.f;
#pragma unroll
        for (int d = 0; d < 32; d++) dot = fmaf(ch[m * 32 + d], q[d], dot);
        const float z = b + a * (dot * rq);
        s[m] = 1.f / (1.f + expf(-z));
    }
    int i0 = 0; float v0 = s[0];
#pragma unroll
    for (int m = 1; m < 16; m++) if (s[m] > v0) { v0 = s[m]; i0 = m; }
    int i1 = -1; float v1 = -1.f;
#pragma unroll
    for (int m = 0; m < 16; m++) if (m != i0 && s[m] > v1) { v1 = s[m]; i1 = m; }

    const float p0 = v0 * v0, p1 = v1 * v1;
    const float inv = 1.f / (p0 + p1 + 1e-6f);
    const size_t o = (size_t)bh * T_TOK + t;
    g_w[o * 2 + 0] = p0 * inv;
    g_w[o * 2 + 1] = p1 * inv;
    g_sel[o] = i0 | (i1 << 8);
}

// ---------------- centers_out partial sums ----------------
__global__ __launch_bounds__(256)
void k_centers()
{
    const int bh = blockIdx.x;
    const int tBase = blockIdx.y * (T_TOK / CSPLIT);
    const int wi = threadIdx.x >> 5, lane = threadIdx.x & 31;

    float acc[16], wacc[16];
#pragma unroll
    for (int m = 0; m < 16; m++) { acc[m] = 0.f; wacc[m] = 0.f; }

#pragma unroll 2
    for (int t = tBase + wi; t < tBase + T_TOK / CSPLIT; t += 8) {
        const size_t o = (size_t)bh * T_TOK + t;
        const float vv = g_v[o * HDIM + lane];
        const float2 w01 = *(const float2*)(g_w + o * 2);
        const int sel = g_sel[o];
        const int i0 = sel & 255, i1 = sel >> 8;
#pragma unroll
        for (int m = 0; m < 16; m++) {
            const float w = (m == i0) ? w01.x : ((m == i1) ? w01.y : 0.f);
            acc[m] = fmaf(w, vv, acc[m]);
            wacc[m] += w;
        }
    }

    __shared__ float sacc[8][16][32];
    __shared__ float swacc[8][16];
#pragma unroll
    for (int m = 0; m < 16; m++) sacc[wi][m][lane] = acc[m];
    if (lane == 0) {
#pragma unroll
        for (int m = 0; m < 16; m++) swacc[wi][m] = wacc[m];
    }
    __syncthreads();

    for (int i = threadIdx.x; i < 512; i += 256) {
        const int m = i >> 5, d = i & 31;
        float s = 0.f;
#pragma unroll
        for (int w = 0; w < 8; w++) s += sacc[w][m][d];
        atomicAdd(&g_coacc[bh * 512 + i], s);
    }
    if (threadIdx.x < 16) {
        float s = 0.f;
#pragma unroll
        for (int w = 0; w < 8; w++) s += swacc[w][threadIdx.x];
        atomicAdd(&g_cnt[bh * 16 + threadIdx.x], s);
    }
}

// ---------------- finalize centers_out ----------------
__global__ void k_cofin()
{
    const int i = blockIdx.x * 256 + threadIdx.x;
    const int bh = i >> 9;
    const int m = (i >> 5) & 15;
    g_co[i] = (g_coacc[i] + g_vc[i]) / (g_cnt[bh * 16 + m] + 1.f);
}

// ---------------- out_tok gather ----------------
__global__ void k_ot()
{
    const int bh = blockIdx.x;
    const int t = blockIdx.y * 256 + threadIdx.x;
    __shared__ float co[16][33];
    {
        const int m = threadIdx.x >> 5, d = threadIdx.x & 31;
        co[m][d]     = g_co[bh * 512 + threadIdx.x];
        co[m + 8][d] = g_co[bh * 512 + 256 + threadIdx.x];
    }
    __syncthreads();
    const size_t o = (size_t)bh * T_TOK + t;
    const float w0 = g_w[o * 2 + 0];
    const float w1 = g_w[o * 2 + 1];
    const int sel = g_sel[o];
    const int i0 = sel & 255, i1 = sel >> 8;
    const int b = bh >> 3, h = bh & 7;
    float* dst = g_ot + ((size_t)t * B_SZ + b) * HD + h * HDIM;
#pragma unroll
    for (int d4 = 0; d4 < 8; d4++) {
        float4 r;
        r.x = w0 * co[i0][d4 * 4 + 0] + w1 * co[i1][d4 * 4 + 0];
        r.y = w0 * co[i0][d4 * 4 + 1] + w1 * co[i1][d4 * 4 + 1];
        r.z = w0 * co[i0][d4 * 4 + 2] + w1 * co[i1][d4 * 4 + 2];
        r.w = w0 * co[i0][d4 * 4 + 3] + w1 * co[i1][d4 * 4 + 3];
        *(float4*)(dst + d4 * 4) = r;
    }
}

// ---------------- launch ----------------
extern "C" void kernel_launch(void* const* d_in, const int* in_sizes, int n_in,
                              void* d_out, int out_size)
{
    const float* x      = (const float*)d_in[0];
    const float* f_w    = (const float*)d_in[1];
    const float* f_b    = (const float*)d_in[2];
    const float* v_w    = (const float*)d_in[3];
    const float* v_b    = (const float*)d_in[4];
    const float* proj_w = (const float*)d_in[5];
    const float* proj_b = (const float*)d_in[6];
    const float* alpha  = (const float*)d_in[7];
    const float* beta   = (const float*)d_in[8];
    float* out = (float*)d_out;

    cudaFuncSetAttribute(k_qgemm, cudaFuncAttributeMaxDynamicSharedMemorySize, DYN_SMEM);
    cudaFuncSetAttribute(k_mgemm, cudaFuncAttributeMaxDynamicSharedMemorySize, DYN_SMEM);

    k_zero<<<BH * M_CT * HDIM / 256, 256>>>();
    k_qgemm<<<dim3(NROWS / 128, 2), 256, DYN_SMEM>>>(x, f_w, f_b);
    k_mgemm<<<dim3(NROWS / 128, 2), 256, DYN_SMEM>>>(x, v_w, v_b, nullptr, 0);
    k_pool<<<BH * M_CT, 256>>>();
    k_sim<<<dim3(BH, T_TOK / 256), 256>>>(alpha, beta);
    k_centers<<<dim3(BH, CSPLIT), 256>>>();
    k_cofin<<<BH * M_CT * HDIM / 256, 256>>>();
    k_ot<<<dim3(BH, T_TOK / 256), 256>>>();
    k_mgemm<<<dim3(NROWS / 128, 2), 256, DYN_SMEM>>>(x /*unused*/, proj_w, proj_b, out, 1);
}

// round 14
// speedup vs baseline: 1.7474x; 1.0210x over previous
#include <cuda_runtime.h>
#include <math.h>
#include <stdint.h>

// R12: delete the proj GEMM + k_ot. Project the 16 centers (k_pco, exact fp32)
// and gather per token (k_mix). GEMMs remain: split-tf32 q + single-tf32 v.

// ---------------- problem constants ----------------
#define T_TOK 4096
#define B_SZ  16
#define CIN   256
#define HEADS 8
#define HDIM  32
#define HD    256
#define SIDE  64
#define M_CT  16
#define BH    128
#define NROWS (T_TOK * B_SZ)   // 65536
#define CSPLIT 4

// ---------------- GEMM tiling (mma.sync m16n8k8 tf32) ----------------
#define KC   32
#define NCH  (CIN / KC)         // 8
#define PADK 36
#define TILE_F (128 * PADK)
#define STAGE_F (2 * TILE_F)
#define DYN_SMEM (2 * STAGE_F * 4)   // 73728 B

// ---------------- scratch ----------------
__device__ float g_q[(size_t)BH * T_TOK * HDIM];
__device__ float g_v[(size_t)BH * T_TOK * HDIM];
__device__ float g_chat[BH * M_CT * HDIM];
__device__ float g_vc[BH * M_CT * HDIM];
__device__ float g_co[BH * M_CT * HDIM];
__device__ float g_coacc[BH * M_CT * HDIM];
__device__ float g_cnt[BH * M_CT];
__device__ float g_w[(size_t)BH * T_TOK * 2];
__device__ int   g_sel[(size_t)BH * T_TOK];
__device__ float g_pco[(size_t)BH * M_CT * HD];   // projected centers, 2MB

// ---------------- helpers ----------------
__device__ __forceinline__ uint32_t smem_u32(const void* p) {
    uint32_t a;
    asm("{ .reg .u64 t; cvta.to.shared.u64 t, %1; cvt.u32.u64 %0, t; }" : "=r"(a) : "l"(p));
    return a;
}
__device__ __forceinline__ void cp16(uint32_t dst, const void* src) {
    asm volatile("cp.async.cg.shared.global [%0], [%1], 16;" :: "r"(dst), "l"(src) : "memory");
}
__device__ __forceinline__ float totf32(float v) {
    uint32_t o;
    asm("cvt.rna.tf32.f32 %0, %1;" : "=r"(o) : "f"(v));
    return __uint_as_float(o);
}
__device__ __forceinline__ void mma_tf32(float* c, const uint32_t* a, const uint32_t* b) {
    asm volatile(
        "mma.sync.aligned.m16n8k8.row.col.f32.tf32.tf32.f32 "
        "{%0,%1,%2,%3},{%4,%5,%6,%7},{%8,%9},{%0,%1,%2,%3};"
        : "+f"(c[0]), "+f"(c[1]), "+f"(c[2]), "+f"(c[3])
        : "r"(a[0]), "r"(a[1]), "r"(a[2]), "r"(a[3]), "r"(b[0]), "r"(b[1]));
}

__device__ __forceinline__ void load_tile(const float* __restrict__ gsrc,
                                          uint32_t sdst, int tid)
{
    const int seg = tid & 7;
    const int r0 = tid >> 3;
#pragma unroll
    for (int i = 0; i < 4; i++) {
        const int r = r0 + i * 32;
        cp16(sdst + (uint32_t)r * (PADK * 4) + seg * 16,
             (const char*)gsrc + (size_t)r * (CIN * 4) + seg * 16);
    }
}

// ---------------- split-tf32 q GEMM (3 MMA terms, fused hi/lo) ----------------
__global__ __launch_bounds__(256, 2)
void k_qgemm(const float* __restrict__ x, const float* __restrict__ f_w,
             const float* __restrict__ f_b)
{
    extern __shared__ float dynf[];
    __shared__ float sbias[128];

    const int tid = threadIdx.x;
    const int wid = tid >> 5;
    const int lane = tid & 31;
    const int group = lane >> 2;
    const int tig = lane & 3;
    const int wm = wid & 1;
    const int wn = wid >> 1;
    const int rowBase = blockIdx.x * 128;
    const int ct = blockIdx.y;

    if (tid < 128) sbias[tid] = f_b[ct * 128 + tid];

    const uint32_t sbase = smem_u32(dynf);
    const float* A = x + (size_t)rowBase * CIN;
    const float* W = f_w + (size_t)(ct * 128) * CIN;

    float acc[4][4][4];
#pragma unroll
    for (int mi = 0; mi < 4; mi++)
#pragma unroll
        for (int ni = 0; ni < 4; ni++)
#pragma unroll
            for (int r = 0; r < 4; r++) acc[mi][ni][r] = 0.f;

#pragma unroll
    for (int p = 0; p < 2; p++) {
        const uint32_t sb = sbase + p * STAGE_F * 4;
        load_tile(A + p * KC, sb, tid);
        load_tile(W + p * KC, sb + TILE_F * 4, tid);
        asm volatile("cp.async.commit_group;" ::: "memory");
    }

#pragma unroll 1
    for (int c = 0; c < NCH; c++) {
        const int s = c & 1;
        const float* As = dynf + s * STAGE_F;
        const float* Bs = As + TILE_F;
        if (c < NCH - 2) asm volatile("cp.async.wait_group 1;" ::: "memory");
        else             asm volatile("cp.async.wait_group 0;" ::: "memory");
        __syncthreads();
#pragma unroll
        for (int kk8 = 0; kk8 < 4; kk8++) {
            const int kk = kk8 * 8;
            uint32_t ah[4][4], al[4][4], bh[4][2], bl[4][2];
#pragma unroll
            for (int mi = 0; mi < 4; mi++) {
                const int r0 = wm * 64 + mi * 16 + group;
                float raw[4];
                raw[0] = As[r0 * PADK + kk + tig];
                raw[1] = As[(r0 + 8) * PADK + kk + tig];
                raw[2] = As[r0 * PADK + kk + tig + 4];
                raw[3] = As[(r0 + 8) * PADK + kk + tig + 4];
#pragma unroll
                for (int r = 0; r < 4; r++) {
                    const float h = totf32(raw[r]);
                    ah[mi][r] = __float_as_uint(h);
                    al[mi][r] = __float_as_uint(totf32(raw[r] - h));
                }
            }
#pragma unroll
            for (int ni = 0; ni < 4; ni++) {
                const int cb = wn * 32 + ni * 8 + group;
                float raw[2];
                raw[0] = Bs[cb * PADK + kk + tig];
                raw[1] = Bs[cb * PADK + kk + tig + 4];
#pragma unroll
                for (int r = 0; r < 2; r++) {
                    const float h = totf32(raw[r]);
                    bh[ni][r] = __float_as_uint(h);
                    bl[ni][r] = __float_as_uint(totf32(raw[r] - h));
                }
            }
#pragma unroll
            for (int mi = 0; mi < 4; mi++)
#pragma unroll
                for (int ni = 0; ni < 4; ni++) {
                    mma_tf32(acc[mi][ni], al[mi], bh[ni]);
                    mma_tf32(acc[mi][ni], ah[mi], bl[ni]);
                    mma_tf32(acc[mi][ni], ah[mi], bh[ni]);
                }
        }
        __syncthreads();
        if (c + 2 < NCH) {
            const uint32_t sb = sbase + s * STAGE_F * 4;
            load_tile(A + (c + 2) * KC, sb, tid);
            load_tile(W + (c + 2) * KC, sb + TILE_F * 4, tid);
            asm volatile("cp.async.commit_group;" ::: "memory");
        }
    }

#pragma unroll
    for (int mi = 0; mi < 4; mi++)
#pragma unroll
        for (int ni = 0; ni < 4; ni++) {
            const int row_l = wm * 64 + mi * 16 + group;
            const int col_l = wn * 32 + ni * 8 + 2 * tig;
            const float bx = sbias[col_l], by = sbias[col_l + 1];
#pragma unroll
            for (int h2 = 0; h2 < 2; h2++) {
                const int n_g = rowBase + row_l + h2 * 8;
                float2 val;
                val.x = acc[mi][ni][h2 * 2 + 0] + bx;
                val.y = acc[mi][ni][h2 * 2 + 1] + by;
                const int t = n_g >> 4, bb = n_g & 15;
                const int cLoc = ct * 128 + col_l;
                const int h = cLoc >> 5, d = cLoc & 31;
                *(float2*)(g_q + (((size_t)bb * HEADS + h) * T_TOK + t) * HDIM + d) = val;
            }
        }
}

// ---------------- single tf32 GEMM (v), fused hi conversion ----------------
__global__ __launch_bounds__(256, 2)
void k_vgemm(const float* __restrict__ x, const float* __restrict__ v_w,
             const float* __restrict__ v_b)
{
    extern __shared__ float dynf[];
    __shared__ float sbias[128];

    const int tid = threadIdx.x;
    const int wid = tid >> 5;
    const int lane = tid & 31;
    const int group = lane >> 2;
    const int tig = lane & 3;
    const int wm = wid & 1;
    const int wn = wid >> 1;
    const int rowBase = blockIdx.x * 128;
    const int ct = blockIdx.y;

    if (tid < 128) sbias[tid] = v_b[ct * 128 + tid];

    const uint32_t sbase = smem_u32(dynf);
    const float* A = x + (size_t)rowBase * CIN;
    const float* W = v_w + (size_t)(ct * 128) * CIN;

    float acc[4][4][4];
#pragma unroll
    for (int mi = 0; mi < 4; mi++)
#pragma unroll
        for (int ni = 0; ni < 4; ni++)
#pragma unroll
            for (int r = 0; r < 4; r++) acc[mi][ni][r] = 0.f;

#pragma unroll
    for (int p = 0; p < 2; p++) {
        const uint32_t sb = sbase + p * STAGE_F * 4;
        load_tile(A + p * KC, sb, tid);
        load_tile(W + p * KC, sb + TILE_F * 4, tid);
        asm volatile("cp.async.commit_group;" ::: "memory");
    }

#pragma unroll 1
    for (int c = 0; c < NCH; c++) {
        const int s = c & 1;
        const float* As = dynf + s * STAGE_F;
        const float* Bs = As + TILE_F;
        if (c < NCH - 2) asm volatile("cp.async.wait_group 1;" ::: "memory");
        else             asm volatile("cp.async.wait_group 0;" ::: "memory");
        __syncthreads();
#pragma unroll
        for (int kk8 = 0; kk8 < 4; kk8++) {
            const int kk = kk8 * 8;
            uint32_t a[4][4], b[4][2];
#pragma unroll
            for (int mi = 0; mi < 4; mi++) {
                const int r0 = wm * 64 + mi * 16 + group;
                a[mi][0] = __float_as_uint(totf32(As[r0 * PADK + kk + tig]));
                a[mi][1] = __float_as_uint(totf32(As[(r0 + 8) * PADK + kk + tig]));
                a[mi][2] = __float_as_uint(totf32(As[r0 * PADK + kk + tig + 4]));
                a[mi][3] = __float_as_uint(totf32(As[(r0 + 8) * PADK + kk + tig + 4]));
            }
#pragma unroll
            for (int ni = 0; ni < 4; ni++) {
                const int cb = wn * 32 + ni * 8 + group;
                b[ni][0] = __float_as_uint(totf32(Bs[cb * PADK + kk + tig]));
                b[ni][1] = __float_as_uint(totf32(Bs[cb * PADK + kk + tig + 4]));
            }
#pragma unroll
            for (int mi = 0; mi < 4; mi++)
#pragma unroll
                for (int ni = 0; ni < 4; ni++)
                    mma_tf32(acc[mi][ni], a[mi], b[ni]);
        }
        __syncthreads();
        if (c + 2 < NCH) {
            const uint32_t sb = sbase + s * STAGE_F * 4;
            load_tile(A + (c + 2) * KC, sb, tid);
            load_tile(W + (c + 2) * KC, sb + TILE_F * 4, tid);
            asm volatile("cp.async.commit_group;" ::: "memory");
        }
    }

#pragma unroll
    for (int mi = 0; mi < 4; mi++)
#pragma unroll
        for (int ni = 0; ni < 4; ni++) {
            const int row_l = wm * 64 + mi * 16 + group;
            const int col_l = wn * 32 + ni * 8 + 2 * tig;
            const float bx = sbias[col_l], by = sbias[col_l + 1];
#pragma unroll
            for (int h2 = 0; h2 < 2; h2++) {
                const int n_g = rowBase + row_l + h2 * 8;
                float2 val;
                val.x = acc[mi][ni][h2 * 2 + 0] + bx;
                val.y = acc[mi][ni][h2 * 2 + 1] + by;
                const int t = n_g >> 4, bb = n_g & 15;
                const int cLoc = ct * 128 + col_l;
                const int h = cLoc >> 5, d = cLoc & 31;
                *(float2*)(g_v + (((size_t)bb * HEADS + h) * T_TOK + t) * HDIM + d) = val;
            }
        }
}

// ---------------- zero accumulators ----------------
__global__ void k_zero()
{
    const int i = blockIdx.x * 256 + threadIdx.x;
    g_coacc[i] = 0.f;
    if (i < BH * M_CT) g_cnt[i] = 0.f;
}

// ---------------- pooling ----------------
__global__ void k_pool()
{
    const int bh = blockIdx.x >> 4;
    const int m  = blockIdx.x & 15;
    const int py = m >> 2, px = m & 3;
    const int ti = threadIdx.x >> 5;
    const int d  = threadIdx.x & 31;

    float sq = 0.f, sv = 0.f;
    for (int j = ti; j < 256; j += 8) {
        const int yi = j >> 4, xi = j & 15;
        const int t = (py * 16 + yi) * SIDE + px * 16 + xi;
        const size_t off = ((size_t)bh * T_TOK + t) * HDIM + d;
        sq += g_q[off];
        sv += g_v[off];
    }
    __shared__ float shq[8][32], shv[8][32];
    shq[ti][d] = sq; shv[ti][d] = sv;
    __syncthreads();
    if (threadIdx.x < 32) {
        const int dd = threadIdx.x;
        float aq = 0.f, av = 0.f;
#pragma unroll
        for (int i = 0; i < 8; i++) { aq += shq[i][dd]; av += shv[i][dd]; }
        aq *= (1.f / 256.f); av *= (1.f / 256.f);
        float nn = aq * aq;
#pragma unroll
        for (int o = 16; o; o >>= 1) nn += __shfl_xor_sync(0xffffffffu, nn, o);
        const float denom = fmaxf(sqrtf(nn), 1e-12f);
        g_chat[bh * (M_CT * HDIM) + m * HDIM + dd] = aq / denom;
        g_vc[bh * (M_CT * HDIM) + m * HDIM + dd] = av;
    }
}

// ---------------- similarity + top-2 ----------------
__global__ void k_sim(const float* __restrict__ alpha, const float* __restrict__ beta)
{
    const int bh = blockIdx.x;
    const int t = blockIdx.y * 256 + threadIdx.x;
    __shared__ float ch[M_CT * HDIM];
    ch[threadIdx.x] = g_chat[bh * 512 + threadIdx.x];
    ch[256 + threadIdx.x] = g_chat[bh * 512 + 256 + threadIdx.x];
    __syncthreads();

    float q[32];
    const float* qp = g_q + ((size_t)bh * T_TOK + t) * HDIM;
#pragma unroll
    for (int i = 0; i < 8; i++) {
        float4 v4 = *(const float4*)(qp + i * 4);
        q[i * 4 + 0] = v4.x; q[i * 4 + 1] = v4.y; q[i * 4 + 2] = v4.z; q[i * 4 + 3] = v4.w;
    }
    float qn = 0.f;
#pragma unroll
    for (int d = 0; d < 32; d++) qn += q[d] * q[d];
    const float rq = 1.f / fmaxf(sqrtf(qn), 1e-12f);
    const float a = alpha[0], b = beta[0];

    float s[16];
#pragma unroll
    for (int m = 0; m < 16; m++) {
        float dot = 0.f;
#pragma unroll
        for (int d = 0; d < 32; d++) dot = fmaf(ch[m * 32 + d], q[d], dot);
        const float z = b + a * (dot * rq);
        s[m] = 1.f / (1.f + expf(-z));
    }
    int i0 = 0; float v0 = s[0];
#pragma unroll
    for (int m = 1; m < 16; m++) if (s[m] > v0) { v0 = s[m]; i0 = m; }
    int i1 = -1; float v1 = -1.f;
#pragma unroll
    for (int m = 0; m < 16; m++) if (m != i0 && s[m] > v1) { v1 = s[m]; i1 = m; }

    const float p0 = v0 * v0, p1 = v1 * v1;
    const float inv = 1.f / (p0 + p1 + 1e-6f);
    const size_t o = (size_t)bh * T_TOK + t;
    g_w[o * 2 + 0] = p0 * inv;
    g_w[o * 2 + 1] = p1 * inv;
    g_sel[o] = i0 | (i1 << 8);
}

// ---------------- centers_out partial sums ----------------
__global__ __launch_bounds__(256)
void k_centers()
{
    const int bh = blockIdx.x;
    const int tBase = blockIdx.y * (T_TOK / CSPLIT);
    const int wi = threadIdx.x >> 5, lane = threadIdx.x & 31;

    float acc[16], wacc[16];
#pragma unroll
    for (int m = 0; m < 16; m++) { acc[m] = 0.f; wacc[m] = 0.f; }

#pragma unroll 2
    for (int t = tBase + wi; t < tBase + T_TOK / CSPLIT; t += 8) {
        const size_t o = (size_t)bh * T_TOK + t;
        const float vv = g_v[o * HDIM + lane];
        const float2 w01 = *(const float2*)(g_w + o * 2);
        const int sel = g_sel[o];
        const int i0 = sel & 255, i1 = sel >> 8;
#pragma unroll
        for (int m = 0; m < 16; m++) {
            const float w = (m == i0) ? w01.x : ((m == i1) ? w01.y : 0.f);
            acc[m] = fmaf(w, vv, acc[m]);
            wacc[m] += w;
        }
    }

    __shared__ float sacc[8][16][32];
    __shared__ float swacc[8][16];
#pragma unroll
    for (int m = 0; m < 16; m++) sacc[wi][m][lane] = acc[m];
    if (lane == 0) {
#pragma unroll
        for (int m = 0; m < 16; m++) swacc[wi][m] = wacc[m];
    }
    __syncthreads();

    for (int i = threadIdx.x; i < 512; i += 256) {
        const int m = i >> 5, d = i & 31;
        float s = 0.f;
#pragma unroll
        for (int w = 0; w < 8; w++) s += sacc[w][m][d];
        atomicAdd(&g_coacc[bh * 512 + i], s);
    }
    if (threadIdx.x < 16) {
        float s = 0.f;
#pragma unroll
        for (int w = 0; w < 8; w++) s += swacc[w][threadIdx.x];
        atomicAdd(&g_cnt[bh * 16 + threadIdx.x], s);
    }
}

// ---------------- finalize centers_out ----------------
__global__ void k_cofin()
{
    const int i = blockIdx.x * 256 + threadIdx.x;
    const int bh = i >> 9;
    const int m = (i >> 5) & 15;
    g_co[i] = (g_coacc[i] + g_vc[i]) / (g_cnt[bh * 16 + m] + 1.f);
}

// ---------------- project centers: pco[bh][m][cout] = proj_w[cout, h*32:+32] . co[bh][m] ----------------
__global__ __launch_bounds__(256)
void k_pco(const float* __restrict__ proj_w)
{
    const int bh = blockIdx.x;
    const int h = bh & 7;
    const int cout = threadIdx.x;
    __shared__ float sco[512];
    sco[cout] = g_co[bh * 512 + cout];
    sco[cout + 256] = g_co[bh * 512 + 256 + cout];
    __syncthreads();

    float wrow[32];
    const float4* wp = (const float4*)(proj_w + (size_t)cout * 256 + h * 32);
#pragma unroll
    for (int i = 0; i < 8; i++) {
        float4 v = wp[i];
        wrow[i * 4 + 0] = v.x; wrow[i * 4 + 1] = v.y;
        wrow[i * 4 + 2] = v.z; wrow[i * 4 + 3] = v.w;
    }
#pragma unroll
    for (int m = 0; m < 16; m++) {
        float s = 0.f;
#pragma unroll
        for (int d = 0; d < 32; d++) s = fmaf(wrow[d], sco[m * 32 + d], s);
        g_pco[((size_t)bh * 16 + m) * HD + cout] = s;
    }
}

// ---------------- final mix: out[t,b,:] = sum_h (w0*pco[i0] + w1*pco[i1]) + proj_b ----------------
// grid (B, T/64), 256 threads; thread = cout, 64 tokens per block, h-sliced smem.
__global__ __launch_bounds__(256)
void k_mix(const float* __restrict__ proj_b, float* __restrict__ out)
{
    const int b = blockIdx.x;
    const int tBase = blockIdx.y * 64;
    const int tid = threadIdx.x;    // = cout

    __shared__ float spco[16 * 256];  // one h slice: [m][cout]
    __shared__ float sw[64 * 2];
    __shared__ int ssel[64];

    float acc[64];
#pragma unroll
    for (int t = 0; t < 64; t++) acc[t] = 0.f;

#pragma unroll 1
    for (int h = 0; h < 8; h++) {
        const int bh = b * 8 + h;
        __syncthreads();
        const float* src = g_pco + (size_t)bh * 16 * HD;
#pragma unroll
        for (int i = 0; i < 16; i++) spco[i * 256 + tid] = src[i * 256 + tid];
        if (tid < 64) {
            const size_t o = (size_t)bh * T_TOK + tBase + tid;
            ((float2*)sw)[tid] = *(const float2*)(g_w + o * 2);
            ssel[tid] = g_sel[o];
        }
        __syncthreads();
#pragma unroll
        for (int t = 0; t < 64; t++) {
            const float w0 = sw[2 * t], w1 = sw[2 * t + 1];
            const int sel = ssel[t];
            const float p0 = spco[(sel & 255) * 256 + tid];   // broadcast
            const float p1 = spco[(sel >> 8) * 256 + tid];    // broadcast
            acc[t] = fmaf(w0, p0, fmaf(w1, p1, acc[t]));
        }
    }
    const float bias = proj_b[tid];
#pragma unroll
    for (int t = 0; t < 64; t++)
        out[((size_t)(tBase + t) * B_SZ + b) * HD + tid] = acc[t] + bias;
}

// ---------------- launch ----------------
extern "C" void kernel_launch(void* const* d_in, const int* in_sizes, int n_in,
                              void* d_out, int out_size)
{
    const float* x      = (const float*)d_in[0];
    const float* f_w    = (const float*)d_in[1];
    const float* f_b    = (const float*)d_in[2];
    const float* v_w    = (const float*)d_in[3];
    const float* v_b    = (const float*)d_in[4];
    const float* proj_w = (const float*)d_in[5];
    const float* proj_b = (const float*)d_in[6];
    const float* alpha  = (const float*)d_in[7];
    const float* beta   = (const float*)d_in[8];
    float* out = (float*)d_out;

    cudaFuncSetAttribute(k_qgemm, cudaFuncAttributeMaxDynamicSharedMemorySize, DYN_SMEM);
    cudaFuncSetAttribute(k_vgemm, cudaFuncAttributeMaxDynamicSharedMemorySize, DYN_SMEM);

    k_zero<<<BH * M_CT * HDIM / 256, 256>>>();
    k_qgemm<<<dim3(NROWS / 128, 2), 256, DYN_SMEM>>>(x, f_w, f_b);
    k_vgemm<<<dim3(NROWS / 128, 2), 256, DYN_SMEM>>>(x, v_w, v_b);
    k_pool<<<BH * M_CT, 256>>>();
    k_sim<<<dim3(BH, T_TOK / 256), 256>>>(alpha, beta);
    k_centers<<<dim3(BH, CSPLIT), 256>>>();
    k_cofin<<<BH * M_CT * HDIM / 256, 256>>>();
    k_pco<<<BH, 256>>>(proj_w);
    k_mix<<<dim3(B_SZ, T_TOK / 64), 256>>>(proj_b, out);
}

// round 15
// speedup vs baseline: 1.7963x; 1.0280x over previous
#include <cuda_runtime.h>
#include <math.h>
#include <stdint.h>

// R15: (1) q-GEMM (3-term split-tf32) and v-GEMM (1-term) merged into ONE
// launch (grid.y=4) for tail packing. (2) k_pool deleted: pooling partials are
// emitted from the GEMM epilogue (per-block, deterministic STG to slot array),
// finalized by k_pfin. Everything downstream unchanged from R14 (465.8us pass).

// ---------------- problem constants ----------------
#define T_TOK 4096
#define B_SZ  16
#define CIN   256
#define HEADS 8
#define HDIM  32
#define HD    256
#define SIDE  64
#define M_CT  16
#define BH    128
#define NROWS (T_TOK * B_SZ)   // 65536
#define CSPLIT 4

// ---------------- GEMM tiling (mma.sync m16n8k8 tf32) ----------------
#define KC   32
#define NCH  (CIN / KC)         // 8
#define PADK 36
#define TILE_F (128 * PADK)
#define STAGE_F (2 * TILE_F)
#define DYN_SMEM (2 * STAGE_F * 4)   // 73728 B

// ---------------- scratch ----------------
__device__ float g_q[(size_t)BH * T_TOK * HDIM];
__device__ float g_v[(size_t)BH * T_TOK * HDIM];
__device__ float g_chat[BH * M_CT * HDIM];
__device__ float g_vc[BH * M_CT * HDIM];
__device__ float g_co[BH * M_CT * HDIM];
__device__ float g_coacc[BH * M_CT * HDIM];
__device__ float g_cnt[BH * M_CT];
__device__ float g_w[(size_t)BH * T_TOK * 2];
__device__ int   g_sel[(size_t)BH * T_TOK];
__device__ float g_pco[(size_t)BH * M_CT * HD];          // projected centers
__device__ float g_ppq[(size_t)BH * M_CT * 32 * 32];     // pool partials q [cell][slot][d]
__device__ float g_ppv[(size_t)BH * M_CT * 32 * 32];     // pool partials v

// ---------------- helpers ----------------
__device__ __forceinline__ uint32_t smem_u32(const void* p) {
    uint32_t a;
    asm("{ .reg .u64 t; cvta.to.shared.u64 t, %1; cvt.u32.u64 %0, t; }" : "=r"(a) : "l"(p));
    return a;
}
__device__ __forceinline__ void cp16(uint32_t dst, const void* src) {
    asm volatile("cp.async.cg.shared.global [%0], [%1], 16;" :: "r"(dst), "l"(src) : "memory");
}
__device__ __forceinline__ float totf32(float v) {
    uint32_t o;
    asm("cvt.rna.tf32.f32 %0, %1;" : "=r"(o) : "f"(v));
    return __uint_as_float(o);
}
__device__ __forceinline__ void mma_tf32(float* c, const uint32_t* a, const uint32_t* b) {
    asm volatile(
        "mma.sync.aligned.m16n8k8.row.col.f32.tf32.tf32.f32 "
        "{%0,%1,%2,%3},{%4,%5,%6,%7},{%8,%9},{%0,%1,%2,%3};"
        : "+f"(c[0]), "+f"(c[1]), "+f"(c[2]), "+f"(c[3])
        : "r"(a[0]), "r"(a[1]), "r"(a[2]), "r"(a[3]), "r"(b[0]), "r"(b[1]));
}

__device__ __forceinline__ void load_tile(const float* __restrict__ gsrc,
                                          uint32_t sdst, int tid)
{
    const int seg = tid & 7;
    const int r0 = tid >> 3;
#pragma unroll
    for (int i = 0; i < 4; i++) {
        const int r = r0 + i * 32;
        cp16(sdst + (uint32_t)r * (PADK * 4) + seg * 16,
             (const char*)gsrc + (size_t)r * (CIN * 4) + seg * 16);
    }
}

// ---------------- merged GEMM: ct<2 -> q (3-term), ct>=2 -> v (1-term) ----------------
__global__ __launch_bounds__(256, 2)
void k_gemm(const float* __restrict__ x,
            const float* __restrict__ f_w, const float* __restrict__ f_b,
            const float* __restrict__ v_w, const float* __restrict__ v_b)
{
    extern __shared__ float dynf[];
    __shared__ float sbias[128];

    const int tid = threadIdx.x;
    const int wid = tid >> 5;
    const int lane = tid & 31;
    const int group = lane >> 2;
    const int tig = lane & 3;
    const int wm = wid & 1;
    const int wn = wid >> 1;
    const int rowBase = blockIdx.x * 128;
    const int ct = blockIdx.y;
    const bool isQ = (ct < 2);
    const int ctl = isQ ? ct : (ct - 2);

    const float* W = (isQ ? f_w : v_w) + (size_t)(ctl * 128) * CIN;
    const float* bias = (isQ ? f_b : v_b) + ctl * 128;
    if (tid < 128) sbias[tid] = bias[tid];

    const uint32_t sbase = smem_u32(dynf);
    const float* A = x + (size_t)rowBase * CIN;

    float acc[4][4][4];
#pragma unroll
    for (int mi = 0; mi < 4; mi++)
#pragma unroll
        for (int ni = 0; ni < 4; ni++)
#pragma unroll
            for (int r = 0; r < 4; r++) acc[mi][ni][r] = 0.f;

#pragma unroll
    for (int p = 0; p < 2; p++) {
        const uint32_t sb = sbase + p * STAGE_F * 4;
        load_tile(A + p * KC, sb, tid);
        load_tile(W + p * KC, sb + TILE_F * 4, tid);
        asm volatile("cp.async.commit_group;" ::: "memory");
    }

#pragma unroll 1
    for (int c = 0; c < NCH; c++) {
        const int s = c & 1;
        const float* As = dynf + s * STAGE_F;
        const float* Bs = As + TILE_F;
        if (c < NCH - 2) asm volatile("cp.async.wait_group 1;" ::: "memory");
        else             asm volatile("cp.async.wait_group 0;" ::: "memory");
        __syncthreads();
        if (isQ) {
#pragma unroll
            for (int kk8 = 0; kk8 < 4; kk8++) {
                const int kk = kk8 * 8;
                uint32_t ah[4][4], al[4][4], bh[4][2], bl[4][2];
#pragma unroll
                for (int mi = 0; mi < 4; mi++) {
                    const int r0 = wm * 64 + mi * 16 + group;
                    float raw[4];
                    raw[0] = As[r0 * PADK + kk + tig];
                    raw[1] = As[(r0 + 8) * PADK + kk + tig];
                    raw[2] = As[r0 * PADK + kk + tig + 4];
                    raw[3] = As[(r0 + 8) * PADK + kk + tig + 4];
#pragma unroll
                    for (int r = 0; r < 4; r++) {
                        const float h = totf32(raw[r]);
                        ah[mi][r] = __float_as_uint(h);
                        al[mi][r] = __float_as_uint(totf32(raw[r] - h));
                    }
                }
#pragma unroll
                for (int ni = 0; ni < 4; ni++) {
                    const int cb = wn * 32 + ni * 8 + group;
                    float raw[2];
                    raw[0] = Bs[cb * PADK + kk + tig];
                    raw[1] = Bs[cb * PADK + kk + tig + 4];
#pragma unroll
                    for (int r = 0; r < 2; r++) {
                        const float h = totf32(raw[r]);
                        bh[ni][r] = __float_as_uint(h);
                        bl[ni][r] = __float_as_uint(totf32(raw[r] - h));
                    }
                }
#pragma unroll
                for (int mi = 0; mi < 4; mi++)
#pragma unroll
                    for (int ni = 0; ni < 4; ni++) {
                        mma_tf32(acc[mi][ni], al[mi], bh[ni]);
                        mma_tf32(acc[mi][ni], ah[mi], bl[ni]);
                        mma_tf32(acc[mi][ni], ah[mi], bh[ni]);
                    }
            }
        } else {
#pragma unroll
            for (int kk8 = 0; kk8 < 4; kk8++) {
                const int kk = kk8 * 8;
                uint32_t a[4][4], b[4][2];
#pragma unroll
                for (int mi = 0; mi < 4; mi++) {
                    const int r0 = wm * 64 + mi * 16 + group;
                    a[mi][0] = __float_as_uint(totf32(As[r0 * PADK + kk + tig]));
                    a[mi][1] = __float_as_uint(totf32(As[(r0 + 8) * PADK + kk + tig]));
                    a[mi][2] = __float_as_uint(totf32(As[r0 * PADK + kk + tig + 4]));
                    a[mi][3] = __float_as_uint(totf32(As[(r0 + 8) * PADK + kk + tig + 4]));
                }
#pragma unroll
                for (int ni = 0; ni < 4; ni++) {
                    const int cb = wn * 32 + ni * 8 + group;
                    b[ni][0] = __float_as_uint(totf32(Bs[cb * PADK + kk + tig]));
                    b[ni][1] = __float_as_uint(totf32(Bs[cb * PADK + kk + tig + 4]));
                }
#pragma unroll
                for (int mi = 0; mi < 4; mi++)
#pragma unroll
                    for (int ni = 0; ni < 4; ni++)
                        mma_tf32(acc[mi][ni], a[mi], b[ni]);
            }
        }
        __syncthreads();
        if (c + 2 < NCH) {
            const uint32_t sb = sbase + s * STAGE_F * 4;
            load_tile(A + (c + 2) * KC, sb, tid);
            load_tile(W + (c + 2) * KC, sb + TILE_F * 4, tid);
            asm volatile("cp.async.commit_group;" ::: "memory");
        }
    }

    // ---- epilogue part 1: biased stores into g_q / g_v ----
    float* const base = isQ ? g_q : g_v;
#pragma unroll
    for (int mi = 0; mi < 4; mi++)
#pragma unroll
        for (int ni = 0; ni < 4; ni++) {
            const int row_l = wm * 64 + mi * 16 + group;
            const int col_l = wn * 32 + ni * 8 + 2 * tig;
            const float bx = sbias[col_l], by = sbias[col_l + 1];
#pragma unroll
            for (int h2 = 0; h2 < 2; h2++) {
                const int n_g = rowBase + row_l + h2 * 8;
                float2 val;
                val.x = acc[mi][ni][h2 * 2 + 0] + bx;
                val.y = acc[mi][ni][h2 * 2 + 1] + by;
                const int t = n_g >> 4, bb = n_g & 15;
                const int cLoc = ctl * 128 + col_l;
                const int h = cLoc >> 5, d = cLoc & 31;
                *(float2*)(base + (((size_t)bb * HEADS + h) * T_TOK + t) * HDIM + d) = val;
            }
        }

    // ---- epilogue part 2: pool partials (pre-bias sums over this block's 8 tokens) ----
    // smem staging is dead after the mainloop's final __syncthreads(); reuse it.
    float* const spool = dynf;   // layout [(wm*4+wn)*16 + b][37] floats, d in 0..31
#pragma unroll
    for (int ni = 0; ni < 4; ni++)
#pragma unroll
        for (int h2 = 0; h2 < 2; h2++)
#pragma unroll
            for (int cc = 0; cc < 2; cc++) {
                float p = acc[0][ni][h2 * 2 + cc] + acc[1][ni][h2 * 2 + cc]
                        + acc[2][ni][h2 * 2 + cc] + acc[3][ni][h2 * 2 + cc];
                const int b = group + 8 * h2;
                const int d = ni * 8 + 2 * tig + cc;
                spool[((wm * 4 + wn) * 16 + b) * 37 + d] = p;
            }
    __syncthreads();

    const int bx_ = blockIdx.x;
    const int m = ((bx_ >> 7) << 2) | ((bx_ >> 1) & 3);          // pool cell (constant/block)
    const int slot = (((bx_ >> 3) & 15) << 1) | (bx_ & 1);       // 0..31 (deterministic)
    float* const pp = isQ ? g_ppq : g_ppv;
    for (int i = tid; i < 2048; i += 256) {
        const int wni = i >> 9, bi = (i >> 5) & 15, di = i & 31;
        const float s = spool[((0 * 4 + wni) * 16 + bi) * 37 + di]
                      + spool[((1 * 4 + wni) * 16 + bi) * 37 + di];
        const int hg = ctl * 4 + wni;
        const int bh = bi * HEADS + hg;
        pp[(((size_t)bh * M_CT + m) * 32 + slot) * 32 + di] = s;
    }
}

// ---------------- pool finalize: slot sums -> chat (normalized) + vc ----------------
__global__ __launch_bounds__(256)
void k_pfin(const float* __restrict__ f_b, const float* __restrict__ v_b)
{
    const int wid = threadIdx.x >> 5, lane = threadIdx.x & 31;
    const int cell = blockIdx.x * 8 + wid;   // (bh*16 + m), 0..2047
    const int bh = cell >> 4;
    const int h = bh & 7;

    const float* pq = g_ppq + (size_t)cell * 1024 + lane;
    const float* pv = g_ppv + (size_t)cell * 1024 + lane;
    float sq = 0.f, sv = 0.f;
#pragma unroll
    for (int s = 0; s < 32; s++) { sq += pq[s * 32]; sv += pv[s * 32]; }

    const float aq = sq * (1.f / 256.f) + f_b[h * 32 + lane];
    const float av = sv * (1.f / 256.f) + v_b[h * 32 + lane];
    float nn = aq * aq;
#pragma unroll
    for (int o = 16; o; o >>= 1) nn += __shfl_xor_sync(0xffffffffu, nn, o);
    const float denom = fmaxf(sqrtf(nn), 1e-12f);
    g_chat[cell * 32 + lane] = aq / denom;
    g_vc[cell * 32 + lane] = av;
}

// ---------------- zero accumulators ----------------
__global__ void k_zero()
{
    const int i = blockIdx.x * 256 + threadIdx.x;
    g_coacc[i] = 0.f;
    if (i < BH * M_CT) g_cnt[i] = 0.f;
}

// ---------------- similarity + top-2 ----------------
__global__ void k_sim(const float* __restrict__ alpha, const float* __restrict__ beta)
{
    const int bh = blockIdx.x;
    const int t = blockIdx.y * 256 + threadIdx.x;
    __shared__ float ch[M_CT * HDIM];
    ch[threadIdx.x] = g_chat[bh * 512 + threadIdx.x];
    ch[256 + threadIdx.x] = g_chat[bh * 512 + 256 + threadIdx.x];
    __syncthreads();

    float q[32];
    const float* qp = g_q + ((size_t)bh * T_TOK + t) * HDIM;
#pragma unroll
    for (int i = 0; i < 8; i++) {
        float4 v4 = *(const float4*)(qp + i * 4);
        q[i * 4 + 0] = v4.x; q[i * 4 + 1] = v4.y; q[i * 4 + 2] = v4.z; q[i * 4 + 3] = v4.w;
    }
    float qn = 0.f;
#pragma unroll
    for (int d = 0; d < 32; d++) qn += q[d] * q[d];
    const float rq = 1.f / fmaxf(sqrtf(qn), 1e-12f);
    const float a = alpha[0], b = beta[0];

    float s[16];
#pragma unroll
    for (int m = 0; m < 16; m++) {
        float dot = 0.f;
#pragma unroll
        for (int d = 0; d < 32; d++) dot = fmaf(ch[m * 32 + d], q[d], dot);
        const float z = b + a * (dot * rq);
        s[m] = 1.f / (1.f + expf(-z));
    }
    int i0 = 0; float v0 = s[0];
#pragma unroll
    for (int m = 1; m < 16; m++) if (s[m] > v0) { v0 = s[m]; i0 = m; }
    int i1 = -1; float v1 = -1.f;
#pragma unroll
    for (int m = 0; m < 16; m++) if (m != i0 && s[m] > v1) { v1 = s[m]; i1 = m; }

    const float p0 = v0 * v0, p1 = v1 * v1;
    const float inv = 1.f / (p0 + p1 + 1e-6f);
    const size_t o = (size_t)bh * T_TOK + t;
    g_w[o * 2 + 0] = p0 * inv;
    g_w[o * 2 + 1] = p1 * inv;
    g_sel[o] = i0 | (i1 << 8);
}

// ---------------- centers_out partial sums ----------------
__global__ __launch_bounds__(256)
void k_centers()
{
    const int bh = blockIdx.x;
    const int tBase = blockIdx.y * (T_TOK / CSPLIT);
    const int wi = threadIdx.x >> 5, lane = threadIdx.x & 31;

    float acc[16], wacc[16];
#pragma unroll
    for (int m = 0; m < 16; m++) { acc[m] = 0.f; wacc[m] = 0.f; }

#pragma unroll 2
    for (int t = tBase + wi; t < tBase + T_TOK / CSPLIT; t += 8) {
        const size_t o = (size_t)bh * T_TOK + t;
        const float vv = g_v[o * HDIM + lane];
        const float2 w01 = *(const float2*)(g_w + o * 2);
        const int sel = g_sel[o];
        const int i0 = sel & 255, i1 = sel >> 8;
#pragma unroll
        for (int m = 0; m < 16; m++) {
            const float w = (m == i0) ? w01.x : ((m == i1) ? w01.y : 0.f);
            acc[m] = fmaf(w, vv, acc[m]);
            wacc[m] += w;
        }
    }

    __shared__ float sacc[8][16][32];
    __shared__ float swacc[8][16];
#pragma unroll
    for (int m = 0; m < 16; m++) sacc[wi][m][lane] = acc[m];
    if (lane == 0) {
#pragma unroll
        for (int m = 0; m < 16; m++) swacc[wi][m] = wacc[m];
    }
    __syncthreads();

    for (int i = threadIdx.x; i < 512; i += 256) {
        const int m = i >> 5, d = i & 31;
        float s = 0.f;
#pragma unroll
        for (int w = 0; w < 8; w++) s += sacc[w][m][d];
        atomicAdd(&g_coacc[bh * 512 + i], s);
    }
    if (threadIdx.x < 16) {
        float s = 0.f;
#pragma unroll
        for (int w = 0; w < 8; w++) s += swacc[w][threadIdx.x];
        atomicAdd(&g_cnt[bh * 16 + threadIdx.x], s);
    }
}

// ---------------- finalize centers_out ----------------
__global__ void k_cofin()
{
    const int i = blockIdx.x * 256 + threadIdx.x;
    const int bh = i >> 9;
    const int m = (i >> 5) & 15;
    g_co[i] = (g_coacc[i] + g_vc[i]) / (g_cnt[bh * 16 + m] + 1.f);
}

// ---------------- project centers ----------------
__global__ __launch_bounds__(256)
void k_pco(const float* __restrict__ proj_w)
{
    const int bh = blockIdx.x;
    const int h = bh & 7;
    const int cout = threadIdx.x;
    __shared__ float sco[512];
    sco[cout] = g_co[bh * 512 + cout];
    sco[cout + 256] = g_co[bh * 512 + 256 + cout];
    __syncthreads();

    float wrow[32];
    const float4* wp = (const float4*)(proj_w + (size_t)cout * 256 + h * 32);
#pragma unroll
    for (int i = 0; i < 8; i++) {
        float4 v = wp[i];
        wrow[i * 4 + 0] = v.x; wrow[i * 4 + 1] = v.y;
        wrow[i * 4 + 2] = v.z; wrow[i * 4 + 3] = v.w;
    }
#pragma unroll
    for (int m = 0; m < 16; m++) {
        float s = 0.f;
#pragma unroll
        for (int d = 0; d < 32; d++) s = fmaf(wrow[d], sco[m * 32 + d], s);
        g_pco[((size_t)bh * 16 + m) * HD + cout] = s;
    }
}

// ---------------- final mix ----------------
__global__ __launch_bounds__(256)
void k_mix(const float* __restrict__ proj_b, float* __restrict__ out)
{
    const int b = blockIdx.x;
    const int tBase = blockIdx.y * 64;
    const int tid = threadIdx.x;    // = cout

    __shared__ float spco[16 * 256];
    __shared__ float sw[64 * 2];
    __shared__ int ssel[64];

    float acc[64];
#pragma unroll
    for (int t = 0; t < 64; t++) acc[t] = 0.f;

#pragma unroll 1
    for (int h = 0; h < 8; h++) {
        const int bh = b * 8 + h;
        __syncthreads();
        const float* src = g_pco + (size_t)bh * 16 * HD;
#pragma unroll
        for (int i = 0; i < 16; i++) spco[i * 256 + tid] = src[i * 256 + tid];
        if (tid < 64) {
            const size_t o = (size_t)bh * T_TOK + tBase + tid;
            ((float2*)sw)[tid] = *(const float2*)(g_w + o * 2);
            ssel[tid] = g_sel[o];
        }
        __syncthreads();
#pragma unroll
        for (int t = 0; t < 64; t++) {
            const float w0 = sw[2 * t], w1 = sw[2 * t + 1];
            const int sel = ssel[t];
            const float p0 = spco[(sel & 255) * 256 + tid];
            const float p1 = spco[(sel >> 8) * 256 + tid];
            acc[t] = fmaf(w0, p0, fmaf(w1, p1, acc[t]));
        }
    }
    const float bias = proj_b[tid];
#pragma unroll
    for (int t = 0; t < 64; t++)
        out[((size_t)(tBase + t) * B_SZ + b) * HD + tid] = acc[t] + bias;
}

// ---------------- launch ----------------
extern "C" void kernel_launch(void* const* d_in, const int* in_sizes, int n_in,
                              void* d_out, int out_size)
{
    const float* x      = (const float*)d_in[0];
    const float* f_w    = (const float*)d_in[1];
    const float* f_b    = (const float*)d_in[2];
    const float* v_w    = (const float*)d_in[3];
    const float* v_b    = (const float*)d_in[4];
    const float* proj_w = (const float*)d_in[5];
    const float* proj_b = (const float*)d_in[6];
    const float* alpha  = (const float*)d_in[7];
    const float* beta   = (const float*)d_in[8];
    float* out = (float*)d_out;

    cudaFuncSetAttribute(k_gemm, cudaFuncAttributeMaxDynamicSharedMemorySize, DYN_SMEM);

    k_zero<<<BH * M_CT * HDIM / 256, 256>>>();
    k_gemm<<<dim3(NROWS / 128, 4), 256, DYN_SMEM>>>(x, f_w, f_b, v_w, v_b);
    k_pfin<<<BH * M_CT / 8, 256>>>(f_b, v_b);
    k_sim<<<dim3(BH, T_TOK / 256), 256>>>(alpha, beta);
    k_centers<<<dim3(BH, CSPLIT), 256>>>();
    k_cofin<<<BH * M_CT * HDIM / 256, 256>>>();
    k_pco<<<BH, 256>>>(proj_w);
    k_mix<<<dim3(B_SZ, T_TOK / 64), 256>>>(proj_b, out);
}